// round 9
// baseline (speedup 1.0000x reference)
#include <cuda_runtime.h>
#include <cuda_bf16.h>
#include <stdint.h>
#include <math.h>

#define BB 8
#define SS 2048
#define DM 1024
#define DK 512
#define DV 512
#define MTOK (BB*SS)   // 16384

// ---------------- scratch (static device allocations) ----------------
__device__ __align__(256) float         g_S  [(size_t)BB*SS*SS];      // 134 MB scores
__device__ __align__(256) __nv_bfloat16 g_sqh[(size_t)MTOK*DM];
__device__ __align__(256) __nv_bfloat16 g_sql[(size_t)MTOK*DM];
__device__ __align__(256) __nv_bfloat16 g_kvh[(size_t)MTOK*DM];
__device__ __align__(256) __nv_bfloat16 g_kvl[(size_t)MTOK*DM];
__device__ __align__(256) __nv_bfloat16 g_wqh[(size_t)DK*DM];
__device__ __align__(256) __nv_bfloat16 g_wql[(size_t)DK*DM];
__device__ __align__(256) __nv_bfloat16 g_wkh[(size_t)DK*DM];
__device__ __align__(256) __nv_bfloat16 g_wkl[(size_t)DK*DM];
__device__ __align__(256) __nv_bfloat16 g_wvh[(size_t)DV*DM];
__device__ __align__(256) __nv_bfloat16 g_wvl[(size_t)DV*DM];
__device__ __align__(256) __nv_bfloat16 g_qh [(size_t)MTOK*DK];
__device__ __align__(256) __nv_bfloat16 g_ql [(size_t)MTOK*DK];
__device__ __align__(256) __nv_bfloat16 g_kh [(size_t)MTOK*DK];
__device__ __align__(256) __nv_bfloat16 g_kl [(size_t)MTOK*DK];
__device__ __align__(256) __nv_bfloat16 g_vth[(size_t)DV*MTOK];      // V^T: [512 x 16384]
__device__ __align__(256) __nv_bfloat16 g_vtl[(size_t)DV*MTOK];
__device__ __align__(256) __nv_bfloat16 g_ph [(size_t)MTOK*SS];      // P hi
__device__ __align__(256) __nv_bfloat16 g_pl [(size_t)MTOK*SS];      // P lo

// ---------------- portable PTX helpers (sm_80+ only) ----------
__device__ __forceinline__ uint32_t s2u(const void* p) {
    return (uint32_t)__cvta_generic_to_shared(p);
}

#define CPA16(dst, src) \
    asm volatile("cp.async.cg.shared.global [%0], [%1], 16;" :: "r"(dst), "l"(src))

#define CPA_COMMIT() asm volatile("cp.async.commit_group;" ::: "memory")
#define CPA_WAIT0()  asm volatile("cp.async.wait_group 0;" ::: "memory")
#define CPA_WAIT1()  asm volatile("cp.async.wait_group 1;" ::: "memory")

#define LDSM_X4(r, addr) \
    asm volatile("ldmatrix.sync.aligned.m8n8.x4.shared.b16 {%0,%1,%2,%3}, [%4];" \
        : "=r"((r)[0]), "=r"((r)[1]), "=r"((r)[2]), "=r"((r)[3]) : "r"(addr))

#define MMA16816(d, a, b) \
    asm volatile("mma.sync.aligned.m16n8k16.row.col.f32.bf16.bf16.f32 " \
        "{%0,%1,%2,%3}, {%4,%5,%6,%7}, {%8,%9}, {%0,%1,%2,%3};" \
        : "+f"((d)[0]), "+f"((d)[1]), "+f"((d)[2]), "+f"((d)[3]) \
        : "r"((a)[0]), "r"((a)[1]), "r"((a)[2]), "r"((a)[3]), \
          "r"((b)[0]), "r"((b)[1]))

// ---------------------------------------------------------------------------
// bf16 MMA GEMM:  C[M x N] = sum over 3 segments of Aseg[M x segK] * Bseg[N x segK]^T
//   seg 0: (A0,B0)  seg 1: (A1,B0)  seg 2: (A0,B1)     (3-term bf16 split)
//   Operands K-major row-major bf16. 128x128 CTA tile, BK=64,
//   3-stage cp.async pipeline + register-level fragment double-buffering
//   (LDSM for ks+1 issued before MMAs of ks), 2 CTAs/SM.
//   Smem row = 64 bf16 = 128 B = 8 x 16B chunks; chunk c stored at c^(row&7).
//   CSKIP: skip tiles strictly above causal diagonal
//   KTRUNC: per-segment K truncated at bm0+128 (attn*V causal)
//   EPI: 0 -> fp32 to Cf ; 1 -> bf16 hi/lo split to Ch/Cl
// ---------------------------------------------------------------------------
template <bool CSKIP, bool KTRUNC, int EPI>
__global__ void __launch_bounds__(256, 2) mma_gemm(
    const __nv_bfloat16* __restrict__ A0, const __nv_bfloat16* __restrict__ A1,
    const __nv_bfloat16* __restrict__ B0, const __nv_bfloat16* __restrict__ B1,
    float* __restrict__ Cf, __nv_bfloat16* __restrict__ Ch, __nv_bfloat16* __restrict__ Cl,
    int segK, int ldA, int ldB, int ldC,
    long long sA, long long sB, long long sC)
{
    extern __shared__ char sm[];
    // per stage: A 128x64 bf16 = 16 KB, B 16 KB  -> 32 KB; 3 stages = 96 KB
    const uint32_t smb = s2u(sm);
    const uint32_t aBuf[3] = { smb,         smb + 32768, smb + 65536 };
    const uint32_t bBuf[3] = { smb + 16384, smb + 49152, smb + 81920 };

    const int bn0 = blockIdx.x * 128;
    const int bm0 = blockIdx.y * 128;
    if (CSKIP && bn0 >= bm0 + 128) return;

    const long long z = blockIdx.z;
    A0 += z * sA; A1 += z * sA; B0 += z * sB; B1 += z * sB;

    const int tid = threadIdx.x, wid = tid >> 5, lane = tid & 31;
    const int warp_m = (wid >> 2) * 64;   // 0 or 64
    const int warp_n = (wid & 3) * 32;    // 0,32,64,96

    int kEnd = segK;
    if (KTRUNC) { int l = bm0 + 128; kEnd = (l < segK) ? l : segK; }
    const int cps   = kEnd >> 6;          // 64-elem chunks per segment
    const int total = 3 * cps;            // >= 6 always

    float acc[4][4][4] = {};

    auto load_chunk = [&](int c, int buf) {
        int seg = c / cps, ck = c - seg * cps;
        const __nv_bfloat16* Aseg = (seg == 1) ? A1 : A0;
        const __nv_bfloat16* Bseg = (seg == 2) ? B1 : B0;
        const __nv_bfloat16* gA = Aseg + (size_t)bm0 * ldA + (ck << 6);
        const __nv_bfloat16* gB = Bseg + (size_t)bn0 * ldB + (ck << 6);
        const uint32_t bA = aBuf[buf], bB = bBuf[buf];
        #pragma unroll
        for (int t = 0; t < 4; ++t) {
            int f = tid + t * 256;            // 0..1023
            int row = f >> 3, cch = f & 7;
            int sw = cch ^ (row & 7);
            CPA16(bA + row * 128 + sw * 16, (const char*)(gA + (size_t)row * ldA) + cch * 16);
            CPA16(bB + row * 128 + sw * 16, (const char*)(gB + (size_t)row * ldB) + cch * 16);
        }
        CPA_COMMIT();
    };

    // prologue: stages 0 and 1 in flight; publish stage 0
    load_chunk(0, 0);
    load_chunk(1, 1);
    CPA_WAIT1();
    __syncthreads();

    const int wi = lane & 7, g = lane >> 3;   // ldmatrix lane-group decomposition

    // per-thread ldmatrix row components (fixed across chunks/ks)
    int arow[4], brow[2];
    #pragma unroll
    for (int mf = 0; mf < 4; ++mf) arow[mf] = warp_m + mf * 16 + (g & 1) * 8 + wi;
    #pragma unroll
    for (int p = 0; p < 2; ++p)    brow[p]  = warp_n + p * 16 + (g >> 1) * 8 + wi;
    const int acsel = g >> 1;   // A chunk-column low bit
    const int bcsel = g & 1;    // B chunk-column low bit

    uint32_t afr[2][4][4];
    uint32_t bfr[2][4][2];

    int buf = 0;
    for (int c = 0; c < total; ++c) {
        const uint32_t bA = aBuf[buf], bB = bBuf[buf];
        int nb = buf + 2; if (nb >= 3) nb -= 3;

        // macro-free frag loader for k-step ks into slot s
        auto load_frags = [&](int ks, int s) {
            #pragma unroll
            for (int mf = 0; mf < 4; ++mf) {
                int cch = 2 * ks + acsel;
                LDSM_X4(afr[s][mf], bA + arow[mf] * 128 + ((cch ^ (arow[mf] & 7)) * 16));
            }
            #pragma unroll
            for (int p = 0; p < 2; ++p) {
                uint32_t r[4];
                int cch = 2 * ks + bcsel;
                LDSM_X4(r, bB + brow[p] * 128 + ((cch ^ (brow[p] & 7)) * 16));
                bfr[s][2 * p + 0][0] = r[0]; bfr[s][2 * p + 0][1] = r[1];
                bfr[s][2 * p + 1][0] = r[2]; bfr[s][2 * p + 1][1] = r[3];
            }
        };

        load_frags(0, 0);

        #pragma unroll
        for (int ks = 0; ks < 4; ++ks) {
            const int cur = ks & 1, nxt = cur ^ 1;
            // overlap next-next chunk's cp.async issue with MMA stream
            if (ks == 1 && c + 2 < total) load_chunk(c + 2, nb);
            // prefetch frags for ks+1 before running MMAs of ks
            if (ks < 3) load_frags(ks + 1, nxt);
            #pragma unroll
            for (int mf = 0; mf < 4; ++mf)
                #pragma unroll
                for (int nf = 0; nf < 4; ++nf)
                    MMA16816(acc[mf][nf], afr[cur][mf], bfr[cur][nf]);
        }

        // single barrier per chunk: publish chunk c+1, retire buffer of chunk c
        if (c + 1 < total) {
            if (c + 2 < total) { CPA_WAIT1(); } else { CPA_WAIT0(); }
            __syncthreads();
        }
        if (++buf == 3) buf = 0;
    }

    // ---- epilogue: c0,c1 -> (row = lane/4, col = (lane%4)*2), c2,c3 -> row+8 ----
    const int rq = lane >> 2, cq = (lane & 3) * 2;
    #pragma unroll
    for (int mf = 0; mf < 4; ++mf) {
        #pragma unroll
        for (int nf = 0; nf < 4; ++nf) {
            int m0 = bm0 + warp_m + mf * 16 + rq;
            int n0 = bn0 + warp_n + nf * 8 + cq;
            if (EPI == 0) {
                float* base = Cf + z * sC;
                *(float2*)(base + (size_t)m0 * ldC + n0) =
                    make_float2(acc[mf][nf][0], acc[mf][nf][1]);
                *(float2*)(base + (size_t)(m0 + 8) * ldC + n0) =
                    make_float2(acc[mf][nf][2], acc[mf][nf][3]);
            } else {
                #pragma unroll
                for (int h = 0; h < 2; ++h) {
                    float v0 = acc[mf][nf][2 * h + 0];
                    float v1 = acc[mf][nf][2 * h + 1];
                    __nv_bfloat16 h0 = __float2bfloat16(v0);
                    __nv_bfloat16 h1 = __float2bfloat16(v1);
                    __nv_bfloat162 HH, LL;
                    HH.x = h0; HH.y = h1;
                    LL.x = __float2bfloat16(v0 - __bfloat162float(h0));
                    LL.y = __float2bfloat16(v1 - __bfloat162float(h1));
                    size_t off = (size_t)(m0 + 8 * h) * ldC + n0;
                    *(__nv_bfloat162*)(Ch + off) = HH;
                    *(__nv_bfloat162*)(Cl + off) = LL;
                }
            }
        }
    }
}

// ---------------------------------------------------------------------------
// fp32 -> bf16 (hi, lo) split for both sources in one launch (grid.y selects)
// ---------------------------------------------------------------------------
__global__ void __launch_bounds__(256) split2_kernel(
    const float* __restrict__ x0, __nv_bfloat16* __restrict__ h0, __nv_bfloat16* __restrict__ l0,
    const float* __restrict__ x1, __nv_bfloat16* __restrict__ h1, __nv_bfloat16* __restrict__ l1)
{
    const float* x = blockIdx.y ? x1 : x0;
    __nv_bfloat16* h = blockIdx.y ? h1 : h0;
    __nv_bfloat16* l = blockIdx.y ? l1 : l0;
    int i = (blockIdx.x * 256 + threadIdx.x) * 8;
    float4 a = *(const float4*)(x + i);
    float4 b = *(const float4*)(x + i + 4);
    float v[8] = {a.x, a.y, a.z, a.w, b.x, b.y, b.z, b.w};
    union { __nv_bfloat16 bb[8]; uint4 u; } H, L;
    #pragma unroll
    for (int j = 0; j < 8; ++j) {
        __nv_bfloat16 hh = __float2bfloat16(v[j]);
        H.bb[j] = hh;
        L.bb[j] = __float2bfloat16(v[j] - __bfloat162float(hh));
    }
    *(uint4*)(h + i) = H.u;
    *(uint4*)(l + i) = L.u;
}

// W [DM x 512] fp32 -> Wt hi/lo [512 x DM] bf16 (transposed, K-major)
// grid.y selects which of the 3 weight matrices
__global__ void __launch_bounds__(256) splitw3_kernel(
    const float* __restrict__ W0, __nv_bfloat16* __restrict__ h0, __nv_bfloat16* __restrict__ l0,
    const float* __restrict__ W1, __nv_bfloat16* __restrict__ h1, __nv_bfloat16* __restrict__ l1,
    const float* __restrict__ W2, __nv_bfloat16* __restrict__ h2, __nv_bfloat16* __restrict__ l2)
{
    const float* W = (blockIdx.y == 0) ? W0 : (blockIdx.y == 1) ? W1 : W2;
    __nv_bfloat16* h = (blockIdx.y == 0) ? h0 : (blockIdx.y == 1) ? h1 : h2;
    __nv_bfloat16* l = (blockIdx.y == 0) ? l0 : (blockIdx.y == 1) ? l1 : l2;
    int o = blockIdx.x * 256 + threadIdx.x;   // o = n*DM + k, n<512
    int n = o >> 10, k = o & 1023;
    float v = W[(size_t)k * 512 + n];
    __nv_bfloat16 hh = __float2bfloat16(v);
    h[o] = hh;
    l[o] = __float2bfloat16(v - __bfloat162float(hh));
}

// ---------------------------------------------------------------------------
// fused mask + softmax reading fp32 scores, writing bf16 hi/lo probabilities
// ---------------------------------------------------------------------------
__global__ void __launch_bounds__(256) softmax_split(
    const float* __restrict__ S, __nv_bfloat16* __restrict__ Ph,
    __nv_bfloat16* __restrict__ Pl,
    const int* __restrict__ qpad, const int* __restrict__ kpad, float scale)
{
    const int r = blockIdx.x;
    const int b = r >> 11, i = r & (SS - 1);
    const float* row = S + (size_t)r * SS;
    const int* kp = kpad + b * SS;
    const bool qp = (qpad[r] != 0);
    const int tid = threadIdx.x, j0 = tid * 8;
    const int lane = tid & 31, warp = tid >> 5;

    float4 a = ((const float4*)(row + j0))[0];
    float4 c = ((const float4*)(row + j0))[1];
    int4 ka = ((const int4*)(kp + j0))[0];
    int4 kb = ((const int4*)(kp + j0))[1];
    float x[8] = {a.x, a.y, a.z, a.w, c.x, c.y, c.z, c.w};
    int km[8] = {ka.x, ka.y, ka.z, ka.w, kb.x, kb.y, kb.z, kb.w};

    float m = -INFINITY;
    #pragma unroll
    for (int u = 0; u < 8; ++u) {
        bool valid = (!qp) && (j0 + u <= i) && (km[u] == 0);
        x[u] = valid ? x[u] * scale : -INFINITY;
        m = fmaxf(m, x[u]);
    }

    __shared__ float redm[8], reds[8];
    #pragma unroll
    for (int o = 16; o; o >>= 1) m = fmaxf(m, __shfl_xor_sync(0xffffffffu, m, o));
    if (lane == 0) redm[warp] = m;
    __syncthreads();
    float bm = -INFINITY;
    #pragma unroll
    for (int w = 0; w < 8; ++w) bm = fmaxf(bm, redm[w]);

    uint4* oh = (uint4*)(Ph + (size_t)r * SS + j0);
    uint4* ol = (uint4*)(Pl + (size_t)r * SS + j0);

    if (bm == -INFINITY) {     // fully masked row -> zeros
        uint4 zz = make_uint4(0, 0, 0, 0);
        *oh = zz; *ol = zz;
        return;
    }

    float e[8];
    float s = 0.0f;
    #pragma unroll
    for (int u = 0; u < 8; ++u) {
        e[u] = (x[u] == -INFINITY) ? 0.0f : __expf(x[u] - bm);
        s += e[u];
    }
    #pragma unroll
    for (int o = 16; o; o >>= 1) s += __shfl_xor_sync(0xffffffffu, s, o);
    if (lane == 0) reds[warp] = s;
    __syncthreads();
    float bs = 0.0f;
    #pragma unroll
    for (int w = 0; w < 8; ++w) bs += reds[w];

    const float rinv = 1.0f / bs;
    union { __nv_bfloat16 bb[8]; uint4 u; } H, L;
    #pragma unroll
    for (int u = 0; u < 8; ++u) {
        float p = e[u] * rinv;
        __nv_bfloat16 hh = __float2bfloat16(p);
        H.bb[u] = hh;
        L.bb[u] = __float2bfloat16(p - __bfloat162float(hh));
    }
    *oh = H.u;
    *ol = L.u;
}

// ---------------------------------------------------------------------------
extern "C" void kernel_launch(void* const* d_in, const int* in_sizes, int n_in,
                              void* d_out, int out_size)
{
    const float* sq   = (const float*)d_in[0];
    const float* skv  = (const float*)d_in[1];
    const int*   qpad = (const int*)d_in[2];
    const int*   kpad = (const int*)d_in[3];
    const float* Wq   = (const float*)d_in[4];
    const float* Wk   = (const float*)d_in[5];
    const float* Wv   = (const float*)d_in[6];
    float* out = (float*)d_out;

    float *Sb;
    __nv_bfloat16 *sqh, *sql, *kvh, *kvl, *wqh, *wql, *wkh, *wkl, *wvh, *wvl;
    __nv_bfloat16 *qh, *ql, *kh, *kl, *vth, *vtl, *pH, *pL;
    cudaGetSymbolAddress((void**)&Sb,  g_S);
    cudaGetSymbolAddress((void**)&sqh, g_sqh); cudaGetSymbolAddress((void**)&sql, g_sql);
    cudaGetSymbolAddress((void**)&kvh, g_kvh); cudaGetSymbolAddress((void**)&kvl, g_kvl);
    cudaGetSymbolAddress((void**)&wqh, g_wqh); cudaGetSymbolAddress((void**)&wql, g_wql);
    cudaGetSymbolAddress((void**)&wkh, g_wkh); cudaGetSymbolAddress((void**)&wkl, g_wkl);
    cudaGetSymbolAddress((void**)&wvh, g_wvh); cudaGetSymbolAddress((void**)&wvl, g_wvl);
    cudaGetSymbolAddress((void**)&qh,  g_qh);  cudaGetSymbolAddress((void**)&ql,  g_ql);
    cudaGetSymbolAddress((void**)&kh,  g_kh);  cudaGetSymbolAddress((void**)&kl,  g_kl);
    cudaGetSymbolAddress((void**)&vth, g_vth); cudaGetSymbolAddress((void**)&vtl, g_vtl);
    cudaGetSymbolAddress((void**)&pH,  g_ph);  cudaGetSymbolAddress((void**)&pL,  g_pl);

    const int SMEMSZ = 98304;   // 3 x (16 KB A + 16 KB B)
    cudaFuncSetAttribute(mma_gemm<false, false, 1>,
                         cudaFuncAttributeMaxDynamicSharedMemorySize, SMEMSZ);
    cudaFuncSetAttribute(mma_gemm<true, false, 0>,
                         cudaFuncAttributeMaxDynamicSharedMemorySize, SMEMSZ);
    cudaFuncSetAttribute(mma_gemm<false, true, 0>,
                         cudaFuncAttributeMaxDynamicSharedMemorySize, SMEMSZ);

    // 1) split both sources to bf16 hi/lo (one launch)
    const int nsrc = MTOK * DM;                    // 16.7M
    split2_kernel<<<dim3(nsrc / 2048, 2), 256>>>(sq, sqh, sql, skv, kvh, kvl);
    // 2) split + transpose all weights (one launch)
    splitw3_kernel<<<dim3((DK * DM) / 256, 3), 256>>>(
        Wq, wqh, wql, Wk, wkh, wkl, Wv, wvh, wvl);

    // 3) Q = sq*Wq  [16384 x 512], split-epilogue
    mma_gemm<false, false, 1><<<dim3(DK / 128, MTOK / 128, 1), 256, SMEMSZ>>>(
        sqh, sql, wqh, wql, nullptr, qh, ql, DM, DM, DM, DK, 0, 0, 0);
    // 4) K = skv*Wk
    mma_gemm<false, false, 1><<<dim3(DK / 128, MTOK / 128, 1), 256, SMEMSZ>>>(
        kvh, kvl, wkh, wkl, nullptr, kh, kl, DM, DM, DM, DK, 0, 0, 0);
    // 5) Vt = Wv^T * skv^T  [512 x 16384], split-epilogue (produced transposed)
    mma_gemm<false, false, 1><<<dim3(MTOK / 128, DV / 128, 1), 256, SMEMSZ>>>(
        wvh, wvl, kvh, kvl, nullptr, vth, vtl, DM, DM, DM, MTOK, 0, 0, 0);

    // 6) scores S_b = Q_b * K_b^T (causal tile-skip), fp32 epilogue
    mma_gemm<true, false, 0><<<dim3(SS / 128, SS / 128, BB), 256, SMEMSZ>>>(
        qh, ql, kh, kl, Sb, nullptr, nullptr, DK, DK, DK, SS,
        (long long)SS * DK, (long long)SS * DK, (long long)SS * SS);

    // 7) mask + softmax -> P hi/lo bf16
    const float scale = 0.04419417382415922f;   // 1/sqrt(512)
    softmax_split<<<MTOK, 256>>>(Sb, pH, pL, qpad, kpad, scale);

    // 8) O_b = P_b * V_b  (K truncated at causal diagonal), fp32 epilogue -> out
    mma_gemm<false, true, 0><<<dim3(DV / 128, SS / 128, BB), 256, SMEMSZ>>>(
        pH, pL, vth, vtl, out, nullptr, nullptr, SS, SS, MTOK, DV,
        (long long)SS * SS, (long long)SS, (long long)SS * DV);
}

// round 10
// speedup vs baseline: 1.1445x; 1.1445x over previous
#include <cuda_runtime.h>
#include <cuda_bf16.h>
#include <stdint.h>
#include <math.h>

#define BB 8
#define SS 2048
#define DM 1024
#define DK 512
#define DV 512
#define MTOK (BB*SS)   // 16384

// ---------------- scratch (static device allocations) ----------------
__device__ __align__(256) float         g_S  [(size_t)BB*SS*SS];      // 134 MB scores
__device__ __align__(256) __nv_bfloat16 g_sqh[(size_t)MTOK*DM];
__device__ __align__(256) __nv_bfloat16 g_sql[(size_t)MTOK*DM];
__device__ __align__(256) __nv_bfloat16 g_kvh[(size_t)MTOK*DM];
__device__ __align__(256) __nv_bfloat16 g_kvl[(size_t)MTOK*DM];
__device__ __align__(256) __nv_bfloat16 g_wqh[(size_t)DK*DM];
__device__ __align__(256) __nv_bfloat16 g_wql[(size_t)DK*DM];
__device__ __align__(256) __nv_bfloat16 g_wkh[(size_t)DK*DM];
__device__ __align__(256) __nv_bfloat16 g_wkl[(size_t)DK*DM];
__device__ __align__(256) __nv_bfloat16 g_wvh[(size_t)DV*DM];
__device__ __align__(256) __nv_bfloat16 g_wvl[(size_t)DV*DM];
__device__ __align__(256) __nv_bfloat16 g_qh [(size_t)MTOK*DK];
__device__ __align__(256) __nv_bfloat16 g_ql [(size_t)MTOK*DK];
__device__ __align__(256) __nv_bfloat16 g_kh [(size_t)MTOK*DK];
__device__ __align__(256) __nv_bfloat16 g_kl [(size_t)MTOK*DK];
__device__ __align__(256) __nv_bfloat16 g_vth[(size_t)DV*MTOK];      // V^T: [512 x 16384]
__device__ __align__(256) __nv_bfloat16 g_vtl[(size_t)DV*MTOK];
__device__ __align__(256) __nv_bfloat16 g_ph [(size_t)MTOK*SS];      // P hi
__device__ __align__(256) __nv_bfloat16 g_pl [(size_t)MTOK*SS];      // P lo

// ---------------- portable PTX helpers (sm_80+ only) ----------
__device__ __forceinline__ uint32_t s2u(const void* p) {
    return (uint32_t)__cvta_generic_to_shared(p);
}

#define CPA16(dst, src) \
    asm volatile("cp.async.cg.shared.global [%0], [%1], 16;" :: "r"(dst), "l"(src))

#define CPA_COMMIT() asm volatile("cp.async.commit_group;" ::: "memory")
#define CPA_WAIT0()  asm volatile("cp.async.wait_group 0;" ::: "memory")
#define CPA_WAIT1()  asm volatile("cp.async.wait_group 1;" ::: "memory")

#define LDSM_X4(r, addr) \
    asm volatile("ldmatrix.sync.aligned.m8n8.x4.shared.b16 {%0,%1,%2,%3}, [%4];" \
        : "=r"((r)[0]), "=r"((r)[1]), "=r"((r)[2]), "=r"((r)[3]) : "r"(addr))

#define MMA16816(d, a, b) \
    asm volatile("mma.sync.aligned.m16n8k16.row.col.f32.bf16.bf16.f32 " \
        "{%0,%1,%2,%3}, {%4,%5,%6,%7}, {%8,%9}, {%0,%1,%2,%3};" \
        : "+f"((d)[0]), "+f"((d)[1]), "+f"((d)[2]), "+f"((d)[3]) \
        : "r"((a)[0]), "r"((a)[1]), "r"((a)[2]), "r"((a)[3]), \
          "r"((b)[0]), "r"((b)[1]))

// ---------------------------------------------------------------------------
// bf16 MMA GEMM:  C[M x N] = sum over 3 segments of Aseg[M x segK] * Bseg[N x segK]^T
//   seg 0: (A0,B0)  seg 1: (A1,B0)  seg 2: (A0,B1)     (3-term bf16 split)
//   Operands K-major row-major bf16. 128x128 CTA tile, BK=64,
//   4 warps (2x2), warp tile 64x64 -> 32 HMMA per 8 LDSM per k-step.
//   3-stage cp.async pipeline, single-sync mainloop, 2 CTAs/SM.
//   Smem row = 64 bf16 = 128 B = 8 x 16B chunks; chunk c stored at c^(row&7).
//   CSKIP: skip tiles strictly above causal diagonal
//   KTRUNC: per-segment K truncated at bm0+128 (attn*V causal)
//   EPI: 0 -> fp32 to Cf ; 1 -> bf16 hi/lo split to Ch/Cl
// ---------------------------------------------------------------------------
template <bool CSKIP, bool KTRUNC, int EPI>
__global__ void __launch_bounds__(128, 2) mma_gemm(
    const __nv_bfloat16* __restrict__ A0, const __nv_bfloat16* __restrict__ A1,
    const __nv_bfloat16* __restrict__ B0, const __nv_bfloat16* __restrict__ B1,
    float* __restrict__ Cf, __nv_bfloat16* __restrict__ Ch, __nv_bfloat16* __restrict__ Cl,
    int segK, int ldA, int ldB, int ldC,
    long long sA, long long sB, long long sC)
{
    extern __shared__ char sm[];
    // per stage: A 128x64 bf16 = 16 KB, B 16 KB  -> 32 KB; 3 stages = 96 KB
    const uint32_t smb = s2u(sm);
    const uint32_t aBuf[3] = { smb,         smb + 32768, smb + 65536 };
    const uint32_t bBuf[3] = { smb + 16384, smb + 49152, smb + 81920 };

    const int bn0 = blockIdx.x * 128;
    const int bm0 = blockIdx.y * 128;
    if (CSKIP && bn0 >= bm0 + 128) return;

    const long long z = blockIdx.z;
    A0 += z * sA; A1 += z * sA; B0 += z * sB; B1 += z * sB;

    const int tid = threadIdx.x, wid = tid >> 5, lane = tid & 31;
    const int warp_m = (wid >> 1) * 64;   // 0 or 64
    const int warp_n = (wid & 1) * 64;    // 0 or 64

    int kEnd = segK;
    if (KTRUNC) { int l = bm0 + 128; kEnd = (l < segK) ? l : segK; }
    const int cps   = kEnd >> 6;          // 64-elem chunks per segment
    const int total = 3 * cps;            // >= 3 always

    float acc[4][8][4] = {};

    auto load_chunk = [&](int c, int buf) {
        int seg = c / cps, ck = c - seg * cps;
        const __nv_bfloat16* Aseg = (seg == 1) ? A1 : A0;
        const __nv_bfloat16* Bseg = (seg == 2) ? B1 : B0;
        const __nv_bfloat16* gA = Aseg + (size_t)bm0 * ldA + (ck << 6);
        const __nv_bfloat16* gB = Bseg + (size_t)bn0 * ldB + (ck << 6);
        const uint32_t bA = aBuf[buf], bB = bBuf[buf];
        #pragma unroll
        for (int t = 0; t < 8; ++t) {
            int f = tid + t * 128;            // 0..1023
            int row = f >> 3, cch = f & 7;
            int sw = cch ^ (row & 7);
            CPA16(bA + row * 128 + sw * 16, (const char*)(gA + (size_t)row * ldA) + cch * 16);
            CPA16(bB + row * 128 + sw * 16, (const char*)(gB + (size_t)row * ldB) + cch * 16);
        }
        CPA_COMMIT();
    };

    // prologue: stages 0 and 1 in flight; publish stage 0
    load_chunk(0, 0);
    load_chunk(1, 1);
    CPA_WAIT1();
    __syncthreads();

    const int wi = lane & 7, g = lane >> 3;   // ldmatrix lane-group decomposition

    int buf = 0;
    for (int c = 0; c < total; ++c) {
        const uint32_t bA = aBuf[buf], bB = bBuf[buf];
        int nb = buf + 2; if (nb >= 3) nb -= 3;

        #pragma unroll
        for (int ks = 0; ks < 4; ++ks) {
            // overlap next-next chunk's cp.async issue with MMA stream
            if (ks == 1 && c + 2 < total) load_chunk(c + 2, nb);

            // A frags: x4 -> mats (m+wi,k0), (m+8+wi,k0), (m+wi,k1), (m+8+wi,k1)
            uint32_t a[4][4];
            #pragma unroll
            for (int mf = 0; mf < 4; ++mf) {
                int row = warp_m + mf * 16 + (g & 1) * 8 + wi;
                int cch = 2 * ks + (g >> 1);
                LDSM_X4(a[mf], bA + row * 128 + (cch ^ (row & 7)) * 16);
            }
            // B frags: x4 packs 2 n-frags -> (n+wi,k0),(n+wi,k1),(n+8+wi,k0),(n+8+wi,k1)
            uint32_t b[8][2];
            #pragma unroll
            for (int p = 0; p < 4; ++p) {
                uint32_t r[4];
                int row = warp_n + p * 16 + (g >> 1) * 8 + wi;
                int cch = 2 * ks + (g & 1);
                LDSM_X4(r, bB + row * 128 + (cch ^ (row & 7)) * 16);
                b[2 * p + 0][0] = r[0]; b[2 * p + 0][1] = r[1];
                b[2 * p + 1][0] = r[2]; b[2 * p + 1][1] = r[3];
            }
            #pragma unroll
            for (int mf = 0; mf < 4; ++mf)
                #pragma unroll
                for (int nf = 0; nf < 8; ++nf)
                    MMA16816(acc[mf][nf], a[mf], b[nf]);
        }

        // single barrier per chunk: publish chunk c+1, retire buffer of chunk c
        if (c + 1 < total) {
            if (c + 2 < total) { CPA_WAIT1(); } else { CPA_WAIT0(); }
            __syncthreads();
        }
        if (++buf == 3) buf = 0;
    }

    // ---- epilogue: c0,c1 -> (row = lane/4, col = (lane%4)*2), c2,c3 -> row+8 ----
    const int rq = lane >> 2, cq = (lane & 3) * 2;
    #pragma unroll
    for (int mf = 0; mf < 4; ++mf) {
        #pragma unroll
        for (int nf = 0; nf < 8; ++nf) {
            int m0 = bm0 + warp_m + mf * 16 + rq;
            int n0 = bn0 + warp_n + nf * 8 + cq;
            if (EPI == 0) {
                float* base = Cf + z * sC;
                *(float2*)(base + (size_t)m0 * ldC + n0) =
                    make_float2(acc[mf][nf][0], acc[mf][nf][1]);
                *(float2*)(base + (size_t)(m0 + 8) * ldC + n0) =
                    make_float2(acc[mf][nf][2], acc[mf][nf][3]);
            } else {
                #pragma unroll
                for (int h = 0; h < 2; ++h) {
                    float v0 = acc[mf][nf][2 * h + 0];
                    float v1 = acc[mf][nf][2 * h + 1];
                    __nv_bfloat16 h0 = __float2bfloat16(v0);
                    __nv_bfloat16 h1 = __float2bfloat16(v1);
                    __nv_bfloat162 HH, LL;
                    HH.x = h0; HH.y = h1;
                    LL.x = __float2bfloat16(v0 - __bfloat162float(h0));
                    LL.y = __float2bfloat16(v1 - __bfloat162float(h1));
                    size_t off = (size_t)(m0 + 8 * h) * ldC + n0;
                    *(__nv_bfloat162*)(Ch + off) = HH;
                    *(__nv_bfloat162*)(Cl + off) = LL;
                }
            }
        }
    }
}

// ---------------------------------------------------------------------------
// fp32 -> bf16 (hi, lo) split for both sources in one launch (grid.y selects)
// ---------------------------------------------------------------------------
__global__ void __launch_bounds__(256) split2_kernel(
    const float* __restrict__ x0, __nv_bfloat16* __restrict__ h0, __nv_bfloat16* __restrict__ l0,
    const float* __restrict__ x1, __nv_bfloat16* __restrict__ h1, __nv_bfloat16* __restrict__ l1)
{
    const float* x = blockIdx.y ? x1 : x0;
    __nv_bfloat16* h = blockIdx.y ? h1 : h0;
    __nv_bfloat16* l = blockIdx.y ? l1 : l0;
    int i = (blockIdx.x * 256 + threadIdx.x) * 8;
    float4 a = *(const float4*)(x + i);
    float4 b = *(const float4*)(x + i + 4);
    float v[8] = {a.x, a.y, a.z, a.w, b.x, b.y, b.z, b.w};
    union { __nv_bfloat16 bb[8]; uint4 u; } H, L;
    #pragma unroll
    for (int j = 0; j < 8; ++j) {
        __nv_bfloat16 hh = __float2bfloat16(v[j]);
        H.bb[j] = hh;
        L.bb[j] = __float2bfloat16(v[j] - __bfloat162float(hh));
    }
    *(uint4*)(h + i) = H.u;
    *(uint4*)(l + i) = L.u;
}

// W [DM x 512] fp32 -> Wt hi/lo [512 x DM] bf16 (transposed, K-major)
// grid.y selects which of the 3 weight matrices
__global__ void __launch_bounds__(256) splitw3_kernel(
    const float* __restrict__ W0, __nv_bfloat16* __restrict__ h0, __nv_bfloat16* __restrict__ l0,
    const float* __restrict__ W1, __nv_bfloat16* __restrict__ h1, __nv_bfloat16* __restrict__ l1,
    const float* __restrict__ W2, __nv_bfloat16* __restrict__ h2, __nv_bfloat16* __restrict__ l2)
{
    const float* W = (blockIdx.y == 0) ? W0 : (blockIdx.y == 1) ? W1 : W2;
    __nv_bfloat16* h = (blockIdx.y == 0) ? h0 : (blockIdx.y == 1) ? h1 : h2;
    __nv_bfloat16* l = (blockIdx.y == 0) ? l0 : (blockIdx.y == 1) ? l1 : l2;
    int o = blockIdx.x * 256 + threadIdx.x;   // o = n*DM + k, n<512
    int n = o >> 10, k = o & 1023;
    float v = W[(size_t)k * 512 + n];
    __nv_bfloat16 hh = __float2bfloat16(v);
    h[o] = hh;
    l[o] = __float2bfloat16(v - __bfloat162float(hh));
}

// ---------------------------------------------------------------------------
// fused mask + softmax reading fp32 scores, writing bf16 hi/lo probabilities
// ---------------------------------------------------------------------------
__global__ void __launch_bounds__(256) softmax_split(
    const float* __restrict__ S, __nv_bfloat16* __restrict__ Ph,
    __nv_bfloat16* __restrict__ Pl,
    const int* __restrict__ qpad, const int* __restrict__ kpad, float scale)
{
    const int r = blockIdx.x;
    const int b = r >> 11, i = r & (SS - 1);
    const float* row = S + (size_t)r * SS;
    const int* kp = kpad + b * SS;
    const bool qp = (qpad[r] != 0);
    const int tid = threadIdx.x, j0 = tid * 8;
    const int lane = tid & 31, warp = tid >> 5;

    float4 a = ((const float4*)(row + j0))[0];
    float4 c = ((const float4*)(row + j0))[1];
    int4 ka = ((const int4*)(kp + j0))[0];
    int4 kb = ((const int4*)(kp + j0))[1];
    float x[8] = {a.x, a.y, a.z, a.w, c.x, c.y, c.z, c.w};
    int km[8] = {ka.x, ka.y, ka.z, ka.w, kb.x, kb.y, kb.z, kb.w};

    float m = -INFINITY;
    #pragma unroll
    for (int u = 0; u < 8; ++u) {
        bool valid = (!qp) && (j0 + u <= i) && (km[u] == 0);
        x[u] = valid ? x[u] * scale : -INFINITY;
        m = fmaxf(m, x[u]);
    }

    __shared__ float redm[8], reds[8];
    #pragma unroll
    for (int o = 16; o; o >>= 1) m = fmaxf(m, __shfl_xor_sync(0xffffffffu, m, o));
    if (lane == 0) redm[warp] = m;
    __syncthreads();
    float bm = -INFINITY;
    #pragma unroll
    for (int w = 0; w < 8; ++w) bm = fmaxf(bm, redm[w]);

    uint4* oh = (uint4*)(Ph + (size_t)r * SS + j0);
    uint4* ol = (uint4*)(Pl + (size_t)r * SS + j0);

    if (bm == -INFINITY) {     // fully masked row -> zeros
        uint4 zz = make_uint4(0, 0, 0, 0);
        *oh = zz; *ol = zz;
        return;
    }

    float e[8];
    float s = 0.0f;
    #pragma unroll
    for (int u = 0; u < 8; ++u) {
        e[u] = (x[u] == -INFINITY) ? 0.0f : __expf(x[u] - bm);
        s += e[u];
    }
    #pragma unroll
    for (int o = 16; o; o >>= 1) s += __shfl_xor_sync(0xffffffffu, s, o);
    if (lane == 0) reds[warp] = s;
    __syncthreads();
    float bs = 0.0f;
    #pragma unroll
    for (int w = 0; w < 8; ++w) bs += reds[w];

    const float rinv = 1.0f / bs;
    union { __nv_bfloat16 bb[8]; uint4 u; } H, L;
    #pragma unroll
    for (int u = 0; u < 8; ++u) {
        float p = e[u] * rinv;
        __nv_bfloat16 hh = __float2bfloat16(p);
        H.bb[u] = hh;
        L.bb[u] = __float2bfloat16(p - __bfloat162float(hh));
    }
    *oh = H.u;
    *ol = L.u;
}

// ---------------------------------------------------------------------------
extern "C" void kernel_launch(void* const* d_in, const int* in_sizes, int n_in,
                              void* d_out, int out_size)
{
    const float* sq   = (const float*)d_in[0];
    const float* skv  = (const float*)d_in[1];
    const int*   qpad = (const int*)d_in[2];
    const int*   kpad = (const int*)d_in[3];
    const float* Wq   = (const float*)d_in[4];
    const float* Wk   = (const float*)d_in[5];
    const float* Wv   = (const float*)d_in[6];
    float* out = (float*)d_out;

    float *Sb;
    __nv_bfloat16 *sqh, *sql, *kvh, *kvl, *wqh, *wql, *wkh, *wkl, *wvh, *wvl;
    __nv_bfloat16 *qh, *ql, *kh, *kl, *vth, *vtl, *pH, *pL;
    cudaGetSymbolAddress((void**)&Sb,  g_S);
    cudaGetSymbolAddress((void**)&sqh, g_sqh); cudaGetSymbolAddress((void**)&sql, g_sql);
    cudaGetSymbolAddress((void**)&kvh, g_kvh); cudaGetSymbolAddress((void**)&kvl, g_kvl);
    cudaGetSymbolAddress((void**)&wqh, g_wqh); cudaGetSymbolAddress((void**)&wql, g_wql);
    cudaGetSymbolAddress((void**)&wkh, g_wkh); cudaGetSymbolAddress((void**)&wkl, g_wkl);
    cudaGetSymbolAddress((void**)&wvh, g_wvh); cudaGetSymbolAddress((void**)&wvl, g_wvl);
    cudaGetSymbolAddress((void**)&qh,  g_qh);  cudaGetSymbolAddress((void**)&ql,  g_ql);
    cudaGetSymbolAddress((void**)&kh,  g_kh);  cudaGetSymbolAddress((void**)&kl,  g_kl);
    cudaGetSymbolAddress((void**)&vth, g_vth); cudaGetSymbolAddress((void**)&vtl, g_vtl);
    cudaGetSymbolAddress((void**)&pH,  g_ph);  cudaGetSymbolAddress((void**)&pL,  g_pl);

    const int SMEMSZ = 98304;   // 3 x (16 KB A + 16 KB B)
    cudaFuncSetAttribute(mma_gemm<false, false, 1>,
                         cudaFuncAttributeMaxDynamicSharedMemorySize, SMEMSZ);
    cudaFuncSetAttribute(mma_gemm<true, false, 0>,
                         cudaFuncAttributeMaxDynamicSharedMemorySize, SMEMSZ);
    cudaFuncSetAttribute(mma_gemm<false, true, 0>,
                         cudaFuncAttributeMaxDynamicSharedMemorySize, SMEMSZ);

    // 1) split both sources to bf16 hi/lo (one launch)
    const int nsrc = MTOK * DM;                    // 16.7M
    split2_kernel<<<dim3(nsrc / 2048, 2), 256>>>(sq, sqh, sql, skv, kvh, kvl);
    // 2) split + transpose all weights (one launch)
    splitw3_kernel<<<dim3((DK * DM) / 256, 3), 256>>>(
        Wq, wqh, wql, Wk, wkh, wkl, Wv, wvh, wvl);

    // 3) Q = sq*Wq  [16384 x 512], split-epilogue
    mma_gemm<false, false, 1><<<dim3(DK / 128, MTOK / 128, 1), 128, SMEMSZ>>>(
        sqh, sql, wqh, wql, nullptr, qh, ql, DM, DM, DM, DK, 0, 0, 0);
    // 4) K = skv*Wk
    mma_gemm<false, false, 1><<<dim3(DK / 128, MTOK / 128, 1), 128, SMEMSZ>>>(
        kvh, kvl, wkh, wkl, nullptr, kh, kl, DM, DM, DM, DK, 0, 0, 0);
    // 5) Vt = Wv^T * skv^T  [512 x 16384], split-epilogue (produced transposed)
    mma_gemm<false, false, 1><<<dim3(MTOK / 128, DV / 128, 1), 128, SMEMSZ>>>(
        wvh, wvl, kvh, kvl, nullptr, vth, vtl, DM, DM, DM, MTOK, 0, 0, 0);

    // 6) scores S_b = Q_b * K_b^T (causal tile-skip), fp32 epilogue
    mma_gemm<true, false, 0><<<dim3(SS / 128, SS / 128, BB), 128, SMEMSZ>>>(
        qh, ql, kh, kl, Sb, nullptr, nullptr, DK, DK, DK, SS,
        (long long)SS * DK, (long long)SS * DK, (long long)SS * SS);

    // 7) mask + softmax -> P hi/lo bf16
    const float scale = 0.04419417382415922f;   // 1/sqrt(512)
    softmax_split<<<MTOK, 256>>>(Sb, pH, pL, qpad, kpad, scale);

    // 8) O_b = P_b * V_b  (K truncated at causal diagonal), fp32 epilogue -> out
    mma_gemm<false, true, 0><<<dim3(DV / 128, SS / 128, BB), 128, SMEMSZ>>>(
        pH, pL, vth, vtl, out, nullptr, nullptr, SS, SS, MTOK, DV,
        (long long)SS * SS, (long long)SS, (long long)SS * DV);
}

// round 11
// speedup vs baseline: 1.1781x; 1.0293x over previous
#include <cuda_runtime.h>
#include <cuda_bf16.h>
#include <stdint.h>
#include <math.h>

#define BB 8
#define SS 2048
#define DM 1024
#define DK 512
#define DV 512
#define MTOK (BB*SS)   // 16384

// ---------------- scratch (static device allocations) ----------------
__device__ __align__(256) float         g_S  [(size_t)BB*SS*SS];      // 134 MB scores
__device__ __align__(256) __nv_bfloat16 g_sqh[(size_t)MTOK*DM];
__device__ __align__(256) __nv_bfloat16 g_sql[(size_t)MTOK*DM];
__device__ __align__(256) __nv_bfloat16 g_kvh[(size_t)MTOK*DM];
__device__ __align__(256) __nv_bfloat16 g_kvl[(size_t)MTOK*DM];
__device__ __align__(256) __nv_bfloat16 g_wqh[(size_t)DK*DM];
__device__ __align__(256) __nv_bfloat16 g_wql[(size_t)DK*DM];
__device__ __align__(256) __nv_bfloat16 g_wkh[(size_t)DK*DM];
__device__ __align__(256) __nv_bfloat16 g_wkl[(size_t)DK*DM];
__device__ __align__(256) __nv_bfloat16 g_wvh[(size_t)DV*DM];
__device__ __align__(256) __nv_bfloat16 g_wvl[(size_t)DV*DM];
__device__ __align__(256) __nv_bfloat16 g_qh [(size_t)MTOK*DK];
__device__ __align__(256) __nv_bfloat16 g_ql [(size_t)MTOK*DK];
__device__ __align__(256) __nv_bfloat16 g_kh [(size_t)MTOK*DK];
__device__ __align__(256) __nv_bfloat16 g_kl [(size_t)MTOK*DK];
__device__ __align__(256) __nv_bfloat16 g_vth[(size_t)DV*MTOK];      // V^T: [512 x 16384]
__device__ __align__(256) __nv_bfloat16 g_vtl[(size_t)DV*MTOK];
__device__ __align__(256) __nv_bfloat16 g_ph [(size_t)MTOK*SS];      // P hi
__device__ __align__(256) __nv_bfloat16 g_pl [(size_t)MTOK*SS];      // P lo

// ---------------- portable PTX helpers (sm_80+ only) ----------
__device__ __forceinline__ uint32_t s2u(const void* p) {
    return (uint32_t)__cvta_generic_to_shared(p);
}

#define CPA16(dst, src) \
    asm volatile("cp.async.cg.shared.global [%0], [%1], 16;" :: "r"(dst), "l"(src))

#define CPA_COMMIT() asm volatile("cp.async.commit_group;" ::: "memory")
#define CPA_WAIT0()  asm volatile("cp.async.wait_group 0;" ::: "memory")
#define CPA_WAIT1()  asm volatile("cp.async.wait_group 1;" ::: "memory")

#define LDSM_X4(r, addr) \
    asm volatile("ldmatrix.sync.aligned.m8n8.x4.shared.b16 {%0,%1,%2,%3}, [%4];" \
        : "=r"((r)[0]), "=r"((r)[1]), "=r"((r)[2]), "=r"((r)[3]) : "r"(addr))

#define MMA16816(d, a, b) \
    asm volatile("mma.sync.aligned.m16n8k16.row.col.f32.bf16.bf16.f32 " \
        "{%0,%1,%2,%3}, {%4,%5,%6,%7}, {%8,%9}, {%0,%1,%2,%3};" \
        : "+f"((d)[0]), "+f"((d)[1]), "+f"((d)[2]), "+f"((d)[3]) \
        : "r"((a)[0]), "r"((a)[1]), "r"((a)[2]), "r"((a)[3]), \
          "r"((b)[0]), "r"((b)[1]))

// ---------------------------------------------------------------------------
// Shared GEMM core: acc += sum over 3 segments of Aseg[128 x segK] * Bseg[128 x segK]^T
//   seg 0: (A0,B0)  seg 1: (A1,B0)  seg 2: (A0,B1)     (3-term bf16 split)
//   4 warps (2x2), warp tile 64x64, BK=64, 3-stage cp.async pipeline,
//   single-sync mainloop. Caller provides 96 KB dynamic smem.
//   Smem row = 64 bf16 = 128 B = 8 x 16B chunks; chunk c stored at c^(row&7).
//   KTRUNC: per-segment K truncated at bm0+128 (attn*V causal)
// ---------------------------------------------------------------------------
template <bool KTRUNC>
__device__ __forceinline__ void gemm_core(
    const __nv_bfloat16* __restrict__ A0, const __nv_bfloat16* __restrict__ A1,
    const __nv_bfloat16* __restrict__ B0, const __nv_bfloat16* __restrict__ B1,
    int bm0, int bn0, int segK, int ldA, int ldB,
    float acc[4][8][4])
{
    extern __shared__ char sm[];
    const uint32_t smb = s2u(sm);
    const uint32_t aBuf[3] = { smb,         smb + 32768, smb + 65536 };
    const uint32_t bBuf[3] = { smb + 16384, smb + 49152, smb + 81920 };

    const int tid = threadIdx.x, wid = tid >> 5, lane = tid & 31;
    const int warp_m = (wid >> 1) * 64;   // 0 or 64
    const int warp_n = (wid & 1) * 64;    // 0 or 64

    int kEnd = segK;
    if (KTRUNC) { int l = bm0 + 128; kEnd = (l < segK) ? l : segK; }
    const int cps   = kEnd >> 6;          // 64-elem chunks per segment
    const int total = 3 * cps;

    auto load_chunk = [&](int c, int buf) {
        int seg = c / cps, ck = c - seg * cps;
        const __nv_bfloat16* Aseg = (seg == 1) ? A1 : A0;
        const __nv_bfloat16* Bseg = (seg == 2) ? B1 : B0;
        const __nv_bfloat16* gA = Aseg + (size_t)bm0 * ldA + (ck << 6);
        const __nv_bfloat16* gB = Bseg + (size_t)bn0 * ldB + (ck << 6);
        const uint32_t bA = aBuf[buf], bB = bBuf[buf];
        #pragma unroll
        for (int t = 0; t < 8; ++t) {
            int f = tid + t * 128;            // 0..1023
            int row = f >> 3, cch = f & 7;
            int sw = cch ^ (row & 7);
            CPA16(bA + row * 128 + sw * 16, (const char*)(gA + (size_t)row * ldA) + cch * 16);
            CPA16(bB + row * 128 + sw * 16, (const char*)(gB + (size_t)row * ldB) + cch * 16);
        }
        CPA_COMMIT();
    };

    load_chunk(0, 0);
    load_chunk(1, 1);
    CPA_WAIT1();
    __syncthreads();

    const int wi = lane & 7, g = lane >> 3;   // ldmatrix lane-group decomposition

    int buf = 0;
    for (int c = 0; c < total; ++c) {
        const uint32_t bA = aBuf[buf], bB = bBuf[buf];
        int nb = buf + 2; if (nb >= 3) nb -= 3;

        #pragma unroll
        for (int ks = 0; ks < 4; ++ks) {
            if (ks == 1 && c + 2 < total) load_chunk(c + 2, nb);

            uint32_t a[4][4];
            #pragma unroll
            for (int mf = 0; mf < 4; ++mf) {
                int row = warp_m + mf * 16 + (g & 1) * 8 + wi;
                int cch = 2 * ks + (g >> 1);
                LDSM_X4(a[mf], bA + row * 128 + (cch ^ (row & 7)) * 16);
            }
            uint32_t b[8][2];
            #pragma unroll
            for (int p = 0; p < 4; ++p) {
                uint32_t r[4];
                int row = warp_n + p * 16 + (g >> 1) * 8 + wi;
                int cch = 2 * ks + (g & 1);
                LDSM_X4(r, bB + row * 128 + (cch ^ (row & 7)) * 16);
                b[2 * p + 0][0] = r[0]; b[2 * p + 0][1] = r[1];
                b[2 * p + 1][0] = r[2]; b[2 * p + 1][1] = r[3];
            }
            #pragma unroll
            for (int mf = 0; mf < 4; ++mf)
                #pragma unroll
                for (int nf = 0; nf < 8; ++nf)
                    MMA16816(acc[mf][nf], a[mf], b[nf]);
        }

        if (c + 1 < total) {
            if (c + 2 < total) { CPA_WAIT1(); } else { CPA_WAIT0(); }
            __syncthreads();
        }
        if (++buf == 3) buf = 0;
    }
}

// epilogue: fp32 store. c-frag map: c0,c1 -> (lane/4, (lane%4)*2), c2,c3 -> row+8
__device__ __forceinline__ void epi_f32(
    float acc[4][8][4], float* __restrict__ Cf, int bm0, int bn0, int ldC)
{
    const int tid = threadIdx.x, wid = tid >> 5, lane = tid & 31;
    const int warp_m = (wid >> 1) * 64, warp_n = (wid & 1) * 64;
    const int rq = lane >> 2, cq = (lane & 3) * 2;
    #pragma unroll
    for (int mf = 0; mf < 4; ++mf)
        #pragma unroll
        for (int nf = 0; nf < 8; ++nf) {
            int m0 = bm0 + warp_m + mf * 16 + rq;
            int n0 = bn0 + warp_n + nf * 8 + cq;
            *(float2*)(Cf + (size_t)m0 * ldC + n0) =
                make_float2(acc[mf][nf][0], acc[mf][nf][1]);
            *(float2*)(Cf + (size_t)(m0 + 8) * ldC + n0) =
                make_float2(acc[mf][nf][2], acc[mf][nf][3]);
        }
}

// epilogue: bf16 hi/lo split store
__device__ __forceinline__ void epi_split(
    float acc[4][8][4], __nv_bfloat16* __restrict__ Ch, __nv_bfloat16* __restrict__ Cl,
    int bm0, int bn0, int ldC)
{
    const int tid = threadIdx.x, wid = tid >> 5, lane = tid & 31;
    const int warp_m = (wid >> 1) * 64, warp_n = (wid & 1) * 64;
    const int rq = lane >> 2, cq = (lane & 3) * 2;
    #pragma unroll
    for (int mf = 0; mf < 4; ++mf)
        #pragma unroll
        for (int nf = 0; nf < 8; ++nf) {
            int m0 = bm0 + warp_m + mf * 16 + rq;
            int n0 = bn0 + warp_n + nf * 8 + cq;
            #pragma unroll
            for (int h = 0; h < 2; ++h) {
                float v0 = acc[mf][nf][2 * h + 0];
                float v1 = acc[mf][nf][2 * h + 1];
                __nv_bfloat16 h0 = __float2bfloat16(v0);
                __nv_bfloat16 h1 = __float2bfloat16(v1);
                __nv_bfloat162 HH, LL;
                HH.x = h0; HH.y = h1;
                LL.x = __float2bfloat16(v0 - __bfloat162float(h0));
                LL.y = __float2bfloat16(v1 - __bfloat162float(h1));
                size_t off = (size_t)(m0 + 8 * h) * ldC + n0;
                *(__nv_bfloat162*)(Ch + off) = HH;
                *(__nv_bfloat162*)(Cl + off) = LL;
            }
        }
}

// ---------------------------------------------------------------------------
// All three projections in ONE launch (1536 CTAs) to kill wave quantization.
// blockIdx.x: [0,512) -> Q, [512,1024) -> K, [1024,1536) -> Vt
// ---------------------------------------------------------------------------
__global__ void __launch_bounds__(128, 2) proj3_kernel(
    const __nv_bfloat16* __restrict__ sqh, const __nv_bfloat16* __restrict__ sql,
    const __nv_bfloat16* __restrict__ kvh, const __nv_bfloat16* __restrict__ kvl,
    const __nv_bfloat16* __restrict__ wqh, const __nv_bfloat16* __restrict__ wql,
    const __nv_bfloat16* __restrict__ wkh, const __nv_bfloat16* __restrict__ wkl,
    const __nv_bfloat16* __restrict__ wvh, const __nv_bfloat16* __restrict__ wvl,
    __nv_bfloat16* __restrict__ qh, __nv_bfloat16* __restrict__ ql,
    __nv_bfloat16* __restrict__ kh, __nv_bfloat16* __restrict__ kl,
    __nv_bfloat16* __restrict__ vth, __nv_bfloat16* __restrict__ vtl)
{
    const int bx = blockIdx.x;
    const int p = bx >> 9;        // 0,1,2
    const int t = bx & 511;
    const __nv_bfloat16 *A0, *A1, *B0, *B1;
    __nv_bfloat16 *Ch, *Cl;
    int bm0, bn0, ldC;
    if (p == 0) {
        A0 = sqh; A1 = sql; B0 = wqh; B1 = wql; Ch = qh; Cl = ql;
        bm0 = (t >> 2) * 128; bn0 = (t & 3) * 128; ldC = DK;
    } else if (p == 1) {
        A0 = kvh; A1 = kvl; B0 = wkh; B1 = wkl; Ch = kh; Cl = kl;
        bm0 = (t >> 2) * 128; bn0 = (t & 3) * 128; ldC = DK;
    } else {
        A0 = wvh; A1 = wvl; B0 = kvh; B1 = kvl; Ch = vth; Cl = vtl;
        bm0 = (t & 3) * 128; bn0 = (t >> 2) * 128; ldC = MTOK;
    }
    float acc[4][8][4] = {};
    gemm_core<false>(A0, A1, B0, B1, bm0, bn0, DM, DM, DM, acc);
    epi_split(acc, Ch, Cl, bm0, bn0, ldC);
}

// ---------------------------------------------------------------------------
// Scores: S_b = Q_b * K_b^T, causal tile-skip, fp32 epilogue
// ---------------------------------------------------------------------------
__global__ void __launch_bounds__(128, 2) scores_kernel(
    const __nv_bfloat16* __restrict__ qh, const __nv_bfloat16* __restrict__ ql,
    const __nv_bfloat16* __restrict__ kh, const __nv_bfloat16* __restrict__ kl,
    float* __restrict__ Sb)
{
    const int bn0 = blockIdx.x * 128;
    const int bm0 = blockIdx.y * 128;
    if (bn0 >= bm0 + 128) return;    // above causal diagonal
    const long long z = blockIdx.z;
    const long long soff = z * (long long)SS * DK;
    float acc[4][8][4] = {};
    gemm_core<false>(qh + soff, ql + soff, kh + soff, kl + soff,
                     bm0, bn0, DK, DK, DK, acc);
    epi_f32(acc, Sb + z * (long long)SS * SS, bm0, bn0, SS);
}

// ---------------------------------------------------------------------------
// attn*V: O_b = P_b * V_b, K truncated at causal diagonal.
// bm order REVERSED (longest-work CTAs first) to fix wave-tail imbalance.
// ---------------------------------------------------------------------------
__global__ void __launch_bounds__(128, 2) attnv_kernel(
    const __nv_bfloat16* __restrict__ pH, const __nv_bfloat16* __restrict__ pL,
    const __nv_bfloat16* __restrict__ vth, const __nv_bfloat16* __restrict__ vtl,
    float* __restrict__ out)
{
    const int bn0 = blockIdx.x * 128;
    const int bm0 = (gridDim.y - 1 - blockIdx.y) * 128;   // longest first
    const long long z = blockIdx.z;
    float acc[4][8][4] = {};
    gemm_core<true>(pH + z * (long long)SS * SS, pL + z * (long long)SS * SS,
                    vth + z * (long long)SS,     vtl + z * (long long)SS,
                    bm0, bn0, SS, SS, MTOK, acc);
    epi_f32(acc, out + z * (long long)SS * DV, bm0, bn0, DV);
}

// ---------------------------------------------------------------------------
// fp32 -> bf16 (hi, lo) split for both sources in one launch (grid.y selects)
// ---------------------------------------------------------------------------
__global__ void __launch_bounds__(256) split2_kernel(
    const float* __restrict__ x0, __nv_bfloat16* __restrict__ h0, __nv_bfloat16* __restrict__ l0,
    const float* __restrict__ x1, __nv_bfloat16* __restrict__ h1, __nv_bfloat16* __restrict__ l1)
{
    const float* x = blockIdx.y ? x1 : x0;
    __nv_bfloat16* h = blockIdx.y ? h1 : h0;
    __nv_bfloat16* l = blockIdx.y ? l1 : l0;
    int i = (blockIdx.x * 256 + threadIdx.x) * 8;
    float4 a = *(const float4*)(x + i);
    float4 b = *(const float4*)(x + i + 4);
    float v[8] = {a.x, a.y, a.z, a.w, b.x, b.y, b.z, b.w};
    union { __nv_bfloat16 bb[8]; uint4 u; } H, L;
    #pragma unroll
    for (int j = 0; j < 8; ++j) {
        __nv_bfloat16 hh = __float2bfloat16(v[j]);
        H.bb[j] = hh;
        L.bb[j] = __float2bfloat16(v[j] - __bfloat162float(hh));
    }
    *(uint4*)(h + i) = H.u;
    *(uint4*)(l + i) = L.u;
}

// W [DM x 512] fp32 -> Wt hi/lo [512 x DM] bf16 (transposed, K-major)
__global__ void __launch_bounds__(256) splitw3_kernel(
    const float* __restrict__ W0, __nv_bfloat16* __restrict__ h0, __nv_bfloat16* __restrict__ l0,
    const float* __restrict__ W1, __nv_bfloat16* __restrict__ h1, __nv_bfloat16* __restrict__ l1,
    const float* __restrict__ W2, __nv_bfloat16* __restrict__ h2, __nv_bfloat16* __restrict__ l2)
{
    const float* W = (blockIdx.y == 0) ? W0 : (blockIdx.y == 1) ? W1 : W2;
    __nv_bfloat16* h = (blockIdx.y == 0) ? h0 : (blockIdx.y == 1) ? h1 : h2;
    __nv_bfloat16* l = (blockIdx.y == 0) ? l0 : (blockIdx.y == 1) ? l1 : l2;
    int o = blockIdx.x * 256 + threadIdx.x;   // o = n*DM + k, n<512
    int n = o >> 10, k = o & 1023;
    float v = W[(size_t)k * 512 + n];
    __nv_bfloat16 hh = __float2bfloat16(v);
    h[o] = hh;
    l[o] = __float2bfloat16(v - __bfloat162float(hh));
}

// ---------------------------------------------------------------------------
// fused mask + softmax reading fp32 scores, writing bf16 hi/lo probabilities
// ---------------------------------------------------------------------------
__global__ void __launch_bounds__(256) softmax_split(
    const float* __restrict__ S, __nv_bfloat16* __restrict__ Ph,
    __nv_bfloat16* __restrict__ Pl,
    const int* __restrict__ qpad, const int* __restrict__ kpad, float scale)
{
    const int r = blockIdx.x;
    const int b = r >> 11, i = r & (SS - 1);
    const float* row = S + (size_t)r * SS;
    const int* kp = kpad + b * SS;
    const bool qp = (qpad[r] != 0);
    const int tid = threadIdx.x, j0 = tid * 8;
    const int lane = tid & 31, warp = tid >> 5;

    float4 a = ((const float4*)(row + j0))[0];
    float4 c = ((const float4*)(row + j0))[1];
    int4 ka = ((const int4*)(kp + j0))[0];
    int4 kb = ((const int4*)(kp + j0))[1];
    float x[8] = {a.x, a.y, a.z, a.w, c.x, c.y, c.z, c.w};
    int km[8] = {ka.x, ka.y, ka.z, ka.w, kb.x, kb.y, kb.z, kb.w};

    float m = -INFINITY;
    #pragma unroll
    for (int u = 0; u < 8; ++u) {
        bool valid = (!qp) && (j0 + u <= i) && (km[u] == 0);
        x[u] = valid ? x[u] * scale : -INFINITY;
        m = fmaxf(m, x[u]);
    }

    __shared__ float redm[8], reds[8];
    #pragma unroll
    for (int o = 16; o; o >>= 1) m = fmaxf(m, __shfl_xor_sync(0xffffffffu, m, o));
    if (lane == 0) redm[warp] = m;
    __syncthreads();
    float bm = -INFINITY;
    #pragma unroll
    for (int w = 0; w < 8; ++w) bm = fmaxf(bm, redm[w]);

    uint4* oh = (uint4*)(Ph + (size_t)r * SS + j0);
    uint4* ol = (uint4*)(Pl + (size_t)r * SS + j0);

    if (bm == -INFINITY) {     // fully masked row -> zeros
        uint4 zz = make_uint4(0, 0, 0, 0);
        *oh = zz; *ol = zz;
        return;
    }

    float e[8];
    float s = 0.0f;
    #pragma unroll
    for (int u = 0; u < 8; ++u) {
        e[u] = (x[u] == -INFINITY) ? 0.0f : __expf(x[u] - bm);
        s += e[u];
    }
    #pragma unroll
    for (int o = 16; o; o >>= 1) s += __shfl_xor_sync(0xffffffffu, s, o);
    if (lane == 0) reds[warp] = s;
    __syncthreads();
    float bs = 0.0f;
    #pragma unroll
    for (int w = 0; w < 8; ++w) bs += reds[w];

    const float rinv = 1.0f / bs;
    union { __nv_bfloat16 bb[8]; uint4 u; } H, L;
    #pragma unroll
    for (int u = 0; u < 8; ++u) {
        float p = e[u] * rinv;
        __nv_bfloat16 hh = __float2bfloat16(p);
        H.bb[u] = hh;
        L.bb[u] = __float2bfloat16(p - __bfloat162float(hh));
    }
    *oh = H.u;
    *ol = L.u;
}

// ---------------------------------------------------------------------------
extern "C" void kernel_launch(void* const* d_in, const int* in_sizes, int n_in,
                              void* d_out, int out_size)
{
    const float* sq   = (const float*)d_in[0];
    const float* skv  = (const float*)d_in[1];
    const int*   qpad = (const int*)d_in[2];
    const int*   kpad = (const int*)d_in[3];
    const float* Wq   = (const float*)d_in[4];
    const float* Wk   = (const float*)d_in[5];
    const float* Wv   = (const float*)d_in[6];
    float* out = (float*)d_out;

    float *Sb;
    __nv_bfloat16 *sqh, *sql, *kvh, *kvl, *wqh, *wql, *wkh, *wkl, *wvh, *wvl;
    __nv_bfloat16 *qh, *ql, *kh, *kl, *vth, *vtl, *pH, *pL;
    cudaGetSymbolAddress((void**)&Sb,  g_S);
    cudaGetSymbolAddress((void**)&sqh, g_sqh); cudaGetSymbolAddress((void**)&sql, g_sql);
    cudaGetSymbolAddress((void**)&kvh, g_kvh); cudaGetSymbolAddress((void**)&kvl, g_kvl);
    cudaGetSymbolAddress((void**)&wqh, g_wqh); cudaGetSymbolAddress((void**)&wql, g_wql);
    cudaGetSymbolAddress((void**)&wkh, g_wkh); cudaGetSymbolAddress((void**)&wkl, g_wkl);
    cudaGetSymbolAddress((void**)&wvh, g_wvh); cudaGetSymbolAddress((void**)&wvl, g_wvl);
    cudaGetSymbolAddress((void**)&qh,  g_qh);  cudaGetSymbolAddress((void**)&ql,  g_ql);
    cudaGetSymbolAddress((void**)&kh,  g_kh);  cudaGetSymbolAddress((void**)&kl,  g_kl);
    cudaGetSymbolAddress((void**)&vth, g_vth); cudaGetSymbolAddress((void**)&vtl, g_vtl);
    cudaGetSymbolAddress((void**)&pH,  g_ph);  cudaGetSymbolAddress((void**)&pL,  g_pl);

    const int SMEMSZ = 98304;   // 3 x (16 KB A + 16 KB B)
    cudaFuncSetAttribute(proj3_kernel,
                         cudaFuncAttributeMaxDynamicSharedMemorySize, SMEMSZ);
    cudaFuncSetAttribute(scores_kernel,
                         cudaFuncAttributeMaxDynamicSharedMemorySize, SMEMSZ);
    cudaFuncSetAttribute(attnv_kernel,
                         cudaFuncAttributeMaxDynamicSharedMemorySize, SMEMSZ);

    // 1) split both sources to bf16 hi/lo (one launch)
    const int nsrc = MTOK * DM;                    // 16.7M
    split2_kernel<<<dim3(nsrc / 2048, 2), 256>>>(sq, sqh, sql, skv, kvh, kvl);
    // 2) split + transpose all weights (one launch)
    splitw3_kernel<<<dim3((DK * DM) / 256, 3), 256>>>(
        Wq, wqh, wql, Wk, wkh, wkl, Wv, wvh, wvl);

    // 3) all three projections in ONE launch (1536 CTAs)
    proj3_kernel<<<1536, 128, SMEMSZ>>>(
        sqh, sql, kvh, kvl, wqh, wql, wkh, wkl, wvh, wvl,
        qh, ql, kh, kl, vth, vtl);

    // 4) scores S_b = Q_b * K_b^T (causal tile-skip), fp32 epilogue
    scores_kernel<<<dim3(SS / 128, SS / 128, BB), 128, SMEMSZ>>>(
        qh, ql, kh, kl, Sb);

    // 5) mask + softmax -> P hi/lo bf16
    const float scale = 0.04419417382415922f;   // 1/sqrt(512)
    softmax_split<<<MTOK, 256>>>(Sb, pH, pL, qpad, kpad, scale);

    // 6) O_b = P_b * V_b (K truncated at causal diagonal, longest-first order)
    attnv_kernel<<<dim3(DV / 128, SS / 128, BB), 128, SMEMSZ>>>(
        pH, pL, vth, vtl, out);
}

// round 12
// speedup vs baseline: 1.3476x; 1.1439x over previous
#include <cuda_runtime.h>
#include <cuda_bf16.h>
#include <cuda_fp16.h>
#include <stdint.h>
#include <math.h>

#define BB 8
#define SS 2048
#define DM 1024
#define DK 512
#define DV 512
#define MTOK (BB*SS)   // 16384

// ---------------- scratch (static device allocations) ----------------
__device__ __align__(256) float         g_S  [(size_t)BB*SS*SS];      // 134 MB scores
__device__ __align__(256) __nv_bfloat16 g_sqh[(size_t)MTOK*DM];
__device__ __align__(256) __nv_bfloat16 g_sql[(size_t)MTOK*DM];
__device__ __align__(256) __nv_bfloat16 g_kvh[(size_t)MTOK*DM];
__device__ __align__(256) __nv_bfloat16 g_kvl[(size_t)MTOK*DM];
__device__ __align__(256) __nv_bfloat16 g_wqh[(size_t)DK*DM];
__device__ __align__(256) __nv_bfloat16 g_wql[(size_t)DK*DM];
__device__ __align__(256) __nv_bfloat16 g_wkh[(size_t)DK*DM];
__device__ __align__(256) __nv_bfloat16 g_wkl[(size_t)DK*DM];
__device__ __align__(256) __nv_bfloat16 g_wvh[(size_t)DV*DM];
__device__ __align__(256) __nv_bfloat16 g_wvl[(size_t)DV*DM];
__device__ __align__(256) __half        g_q16[(size_t)MTOK*DK];       // Q fp16 (scores 1-term)
__device__ __align__(256) __half        g_k16[(size_t)MTOK*DK];       // K fp16
__device__ __align__(256) __nv_bfloat16 g_vth[(size_t)DV*MTOK];      // V^T: [512 x 16384]
__device__ __align__(256) __nv_bfloat16 g_vtl[(size_t)DV*MTOK];
__device__ __align__(256) __nv_bfloat16 g_ph [(size_t)MTOK*SS];      // P hi
__device__ __align__(256) __nv_bfloat16 g_pl [(size_t)MTOK*SS];      // P lo

// ---------------- portable PTX helpers (sm_80+ only) ----------
__device__ __forceinline__ uint32_t s2u(const void* p) {
    return (uint32_t)__cvta_generic_to_shared(p);
}

#define CPA16(dst, src) \
    asm volatile("cp.async.cg.shared.global [%0], [%1], 16;" :: "r"(dst), "l"(src))

#define CPA_COMMIT() asm volatile("cp.async.commit_group;" ::: "memory")
#define CPA_WAIT0()  asm volatile("cp.async.wait_group 0;" ::: "memory")
#define CPA_WAIT1()  asm volatile("cp.async.wait_group 1;" ::: "memory")

#define LDSM_X4(r, addr) \
    asm volatile("ldmatrix.sync.aligned.m8n8.x4.shared.b16 {%0,%1,%2,%3}, [%4];" \
        : "=r"((r)[0]), "=r"((r)[1]), "=r"((r)[2]), "=r"((r)[3]) : "r"(addr))

#define MMA16816(d, a, b) \
    asm volatile("mma.sync.aligned.m16n8k16.row.col.f32.bf16.bf16.f32 " \
        "{%0,%1,%2,%3}, {%4,%5,%6,%7}, {%8,%9}, {%0,%1,%2,%3};" \
        : "+f"((d)[0]), "+f"((d)[1]), "+f"((d)[2]), "+f"((d)[3]) \
        : "r"((a)[0]), "r"((a)[1]), "r"((a)[2]), "r"((a)[3]), \
          "r"((b)[0]), "r"((b)[1]))

#define MMA16816H(d, a, b) \
    asm volatile("mma.sync.aligned.m16n8k16.row.col.f32.f16.f16.f32 " \
        "{%0,%1,%2,%3}, {%4,%5,%6,%7}, {%8,%9}, {%0,%1,%2,%3};" \
        : "+f"((d)[0]), "+f"((d)[1]), "+f"((d)[2]), "+f"((d)[3]) \
        : "r"((a)[0]), "r"((a)[1]), "r"((a)[2]), "r"((a)[3]), \
          "r"((b)[0]), "r"((b)[1]))

// ---------------------------------------------------------------------------
// Shared GEMM core.
//   NSEG==3: acc += A0*B0^T + A1*B0^T + A0*B1^T   (3-term bf16 split)
//   NSEG==1: acc += A0*B0^T                        (single term; F16H -> fp16 mma)
//   4 warps (2x2), warp tile 64x64, BK=64, 3-stage cp.async pipeline,
//   single-sync mainloop. Caller provides 96 KB dynamic smem.
//   Smem row = 64 elems = 128 B = 8 x 16B chunks; chunk c stored at c^(row&7).
//   KTRUNC: per-segment K truncated at bm0+128 (attn*V causal)
// Operand element size is 2 bytes (bf16 or fp16) — address math identical.
// ---------------------------------------------------------------------------
template <int NSEG, bool KTRUNC, bool F16H>
__device__ __forceinline__ void gemm_core(
    const __nv_bfloat16* __restrict__ A0, const __nv_bfloat16* __restrict__ A1,
    const __nv_bfloat16* __restrict__ B0, const __nv_bfloat16* __restrict__ B1,
    int bm0, int bn0, int segK, int ldA, int ldB,
    float acc[4][8][4])
{
    extern __shared__ char sm[];
    const uint32_t smb = s2u(sm);
    const uint32_t aBuf[3] = { smb,         smb + 32768, smb + 65536 };
    const uint32_t bBuf[3] = { smb + 16384, smb + 49152, smb + 81920 };

    const int tid = threadIdx.x, wid = tid >> 5, lane = tid & 31;
    const int warp_m = (wid >> 1) * 64;   // 0 or 64
    const int warp_n = (wid & 1) * 64;    // 0 or 64

    int kEnd = segK;
    if (KTRUNC) { int l = bm0 + 128; kEnd = (l < segK) ? l : segK; }
    const int cps   = kEnd >> 6;          // 64-elem chunks per segment
    const int total = NSEG * cps;

    auto load_chunk = [&](int c, int buf) {
        int seg = (NSEG == 1) ? 0 : (c / cps);
        int ck  = (NSEG == 1) ? c : (c - seg * cps);
        const __nv_bfloat16* Aseg = (seg == 1) ? A1 : A0;
        const __nv_bfloat16* Bseg = (seg == 2) ? B1 : B0;
        const __nv_bfloat16* gA = Aseg + (size_t)bm0 * ldA + (ck << 6);
        const __nv_bfloat16* gB = Bseg + (size_t)bn0 * ldB + (ck << 6);
        const uint32_t bA = aBuf[buf], bB = bBuf[buf];
        #pragma unroll
        for (int t = 0; t < 8; ++t) {
            int f = tid + t * 128;            // 0..1023
            int row = f >> 3, cch = f & 7;
            int sw = cch ^ (row & 7);
            CPA16(bA + row * 128 + sw * 16, (const char*)(gA + (size_t)row * ldA) + cch * 16);
            CPA16(bB + row * 128 + sw * 16, (const char*)(gB + (size_t)row * ldB) + cch * 16);
        }
        CPA_COMMIT();
    };

    load_chunk(0, 0);
    load_chunk(1, 1);
    CPA_WAIT1();
    __syncthreads();

    const int wi = lane & 7, g = lane >> 3;   // ldmatrix lane-group decomposition

    int buf = 0;
    for (int c = 0; c < total; ++c) {
        const uint32_t bA = aBuf[buf], bB = bBuf[buf];
        int nb = buf + 2; if (nb >= 3) nb -= 3;

        #pragma unroll
        for (int ks = 0; ks < 4; ++ks) {
            if (ks == 1 && c + 2 < total) load_chunk(c + 2, nb);

            uint32_t a[4][4];
            #pragma unroll
            for (int mf = 0; mf < 4; ++mf) {
                int row = warp_m + mf * 16 + (g & 1) * 8 + wi;
                int cch = 2 * ks + (g >> 1);
                LDSM_X4(a[mf], bA + row * 128 + (cch ^ (row & 7)) * 16);
            }
            uint32_t b[8][2];
            #pragma unroll
            for (int p = 0; p < 4; ++p) {
                uint32_t r[4];
                int row = warp_n + p * 16 + (g >> 1) * 8 + wi;
                int cch = 2 * ks + (g & 1);
                LDSM_X4(r, bB + row * 128 + (cch ^ (row & 7)) * 16);
                b[2 * p + 0][0] = r[0]; b[2 * p + 0][1] = r[1];
                b[2 * p + 1][0] = r[2]; b[2 * p + 1][1] = r[3];
            }
            #pragma unroll
            for (int mf = 0; mf < 4; ++mf)
                #pragma unroll
                for (int nf = 0; nf < 8; ++nf) {
                    if (F16H) { MMA16816H(acc[mf][nf], a[mf], b[nf]); }
                    else      { MMA16816 (acc[mf][nf], a[mf], b[nf]); }
                }
        }

        if (c + 1 < total) {
            if (c + 2 < total) { CPA_WAIT1(); } else { CPA_WAIT0(); }
            __syncthreads();
        }
        if (++buf == 3) buf = 0;
    }
}

// epilogue: fp32 store. c-frag map: c0,c1 -> (lane/4, (lane%4)*2), c2,c3 -> row+8
__device__ __forceinline__ void epi_f32(
    float acc[4][8][4], float* __restrict__ Cf, int bm0, int bn0, int ldC)
{
    const int tid = threadIdx.x, wid = tid >> 5, lane = tid & 31;
    const int warp_m = (wid >> 1) * 64, warp_n = (wid & 1) * 64;
    const int rq = lane >> 2, cq = (lane & 3) * 2;
    #pragma unroll
    for (int mf = 0; mf < 4; ++mf)
        #pragma unroll
        for (int nf = 0; nf < 8; ++nf) {
            int m0 = bm0 + warp_m + mf * 16 + rq;
            int n0 = bn0 + warp_n + nf * 8 + cq;
            *(float2*)(Cf + (size_t)m0 * ldC + n0) =
                make_float2(acc[mf][nf][0], acc[mf][nf][1]);
            *(float2*)(Cf + (size_t)(m0 + 8) * ldC + n0) =
                make_float2(acc[mf][nf][2], acc[mf][nf][3]);
        }
}

// epilogue: bf16 hi/lo split store
__device__ __forceinline__ void epi_split(
    float acc[4][8][4], __nv_bfloat16* __restrict__ Ch, __nv_bfloat16* __restrict__ Cl,
    int bm0, int bn0, int ldC)
{
    const int tid = threadIdx.x, wid = tid >> 5, lane = tid & 31;
    const int warp_m = (wid >> 1) * 64, warp_n = (wid & 1) * 64;
    const int rq = lane >> 2, cq = (lane & 3) * 2;
    #pragma unroll
    for (int mf = 0; mf < 4; ++mf)
        #pragma unroll
        for (int nf = 0; nf < 8; ++nf) {
            int m0 = bm0 + warp_m + mf * 16 + rq;
            int n0 = bn0 + warp_n + nf * 8 + cq;
            #pragma unroll
            for (int h = 0; h < 2; ++h) {
                float v0 = acc[mf][nf][2 * h + 0];
                float v1 = acc[mf][nf][2 * h + 1];
                __nv_bfloat16 h0 = __float2bfloat16(v0);
                __nv_bfloat16 h1 = __float2bfloat16(v1);
                __nv_bfloat162 HH, LL;
                HH.x = h0; HH.y = h1;
                LL.x = __float2bfloat16(v0 - __bfloat162float(h0));
                LL.y = __float2bfloat16(v1 - __bfloat162float(h1));
                size_t off = (size_t)(m0 + 8 * h) * ldC + n0;
                *(__nv_bfloat162*)(Ch + off) = HH;
                *(__nv_bfloat162*)(Cl + off) = LL;
            }
        }
}

// epilogue: single fp16 store (for Q/K feeding the 1-term fp16 scores GEMM)
__device__ __forceinline__ void epi_f16(
    float acc[4][8][4], __half* __restrict__ C, int bm0, int bn0, int ldC)
{
    const int tid = threadIdx.x, wid = tid >> 5, lane = tid & 31;
    const int warp_m = (wid >> 1) * 64, warp_n = (wid & 1) * 64;
    const int rq = lane >> 2, cq = (lane & 3) * 2;
    #pragma unroll
    for (int mf = 0; mf < 4; ++mf)
        #pragma unroll
        for (int nf = 0; nf < 8; ++nf) {
            int m0 = bm0 + warp_m + mf * 16 + rq;
            int n0 = bn0 + warp_n + nf * 8 + cq;
            #pragma unroll
            for (int h = 0; h < 2; ++h) {
                __half2 v = __floats2half2_rn(acc[mf][nf][2 * h + 0],
                                              acc[mf][nf][2 * h + 1]);
                *(__half2*)(C + (size_t)(m0 + 8 * h) * ldC + n0) = v;
            }
        }
}

// ---------------------------------------------------------------------------
// All three projections in ONE launch (1536 CTAs).
// blockIdx.x: [0,512) -> Q (fp16 out), [512,1024) -> K (fp16 out),
//             [1024,1536) -> Vt (bf16 hi/lo out)
// All use 3-term bf16 GEMM internally (full precision accumulate).
// ---------------------------------------------------------------------------
__global__ void __launch_bounds__(128, 2) proj3_kernel(
    const __nv_bfloat16* __restrict__ sqh, const __nv_bfloat16* __restrict__ sql,
    const __nv_bfloat16* __restrict__ kvh, const __nv_bfloat16* __restrict__ kvl,
    const __nv_bfloat16* __restrict__ wqh, const __nv_bfloat16* __restrict__ wql,
    const __nv_bfloat16* __restrict__ wkh, const __nv_bfloat16* __restrict__ wkl,
    const __nv_bfloat16* __restrict__ wvh, const __nv_bfloat16* __restrict__ wvl,
    __half* __restrict__ q16, __half* __restrict__ k16,
    __nv_bfloat16* __restrict__ vth, __nv_bfloat16* __restrict__ vtl)
{
    const int bx = blockIdx.x;
    const int p = bx >> 9;        // 0,1,2
    const int t = bx & 511;
    float acc[4][8][4] = {};
    if (p == 0) {
        int bm0 = (t >> 2) * 128, bn0 = (t & 3) * 128;
        gemm_core<3, false, false>(sqh, sql, wqh, wql, bm0, bn0, DM, DM, DM, acc);
        epi_f16(acc, q16, bm0, bn0, DK);
    } else if (p == 1) {
        int bm0 = (t >> 2) * 128, bn0 = (t & 3) * 128;
        gemm_core<3, false, false>(kvh, kvl, wkh, wkl, bm0, bn0, DM, DM, DM, acc);
        epi_f16(acc, k16, bm0, bn0, DK);
    } else {
        int bm0 = (t & 3) * 128, bn0 = (t >> 2) * 128;
        gemm_core<3, false, false>(wvh, wvl, kvh, kvl, bm0, bn0, DM, DM, DM, acc);
        epi_split(acc, vth, vtl, bm0, bn0, MTOK);
    }
}

// ---------------------------------------------------------------------------
// Scores: S_b = Q_b * K_b^T, 1-term fp16, causal tile-skip, fp32 epilogue
// ---------------------------------------------------------------------------
__global__ void __launch_bounds__(128, 2) scores_kernel(
    const __half* __restrict__ q16, const __half* __restrict__ k16,
    float* __restrict__ Sb)
{
    const int bn0 = blockIdx.x * 128;
    const int bm0 = blockIdx.y * 128;
    if (bn0 >= bm0 + 128) return;    // above causal diagonal
    const long long z = blockIdx.z;
    const long long soff = z * (long long)SS * DK;
    float acc[4][8][4] = {};
    gemm_core<1, false, true>(
        (const __nv_bfloat16*)(q16 + soff), nullptr,
        (const __nv_bfloat16*)(k16 + soff), nullptr,
        bm0, bn0, DK, DK, DK, acc);
    epi_f32(acc, Sb + z * (long long)SS * SS, bm0, bn0, SS);
}

// ---------------------------------------------------------------------------
// attn*V: O_b = P_b * V_b, 3-term bf16, K truncated at causal diagonal.
// bm order REVERSED (longest-work CTAs first).
// ---------------------------------------------------------------------------
__global__ void __launch_bounds__(128, 2) attnv_kernel(
    const __nv_bfloat16* __restrict__ pH, const __nv_bfloat16* __restrict__ pL,
    const __nv_bfloat16* __restrict__ vth, const __nv_bfloat16* __restrict__ vtl,
    float* __restrict__ out)
{
    const int bn0 = blockIdx.x * 128;
    const int bm0 = (gridDim.y - 1 - blockIdx.y) * 128;   // longest first
    const long long z = blockIdx.z;
    float acc[4][8][4] = {};
    gemm_core<3, true, false>(
        pH + z * (long long)SS * SS, pL + z * (long long)SS * SS,
        vth + z * (long long)SS,     vtl + z * (long long)SS,
        bm0, bn0, SS, SS, MTOK, acc);
    epi_f32(acc, out + z * (long long)SS * DV, bm0, bn0, DV);
}

// ---------------------------------------------------------------------------
// fp32 -> bf16 (hi, lo) split for both sources in one launch (grid.y selects)
// ---------------------------------------------------------------------------
__global__ void __launch_bounds__(256) split2_kernel(
    const float* __restrict__ x0, __nv_bfloat16* __restrict__ h0, __nv_bfloat16* __restrict__ l0,
    const float* __restrict__ x1, __nv_bfloat16* __restrict__ h1, __nv_bfloat16* __restrict__ l1)
{
    const float* x = blockIdx.y ? x1 : x0;
    __nv_bfloat16* h = blockIdx.y ? h1 : h0;
    __nv_bfloat16* l = blockIdx.y ? l1 : l0;
    int i = (blockIdx.x * 256 + threadIdx.x) * 8;
    float4 a = *(const float4*)(x + i);
    float4 b = *(const float4*)(x + i + 4);
    float v[8] = {a.x, a.y, a.z, a.w, b.x, b.y, b.z, b.w};
    union { __nv_bfloat16 bb[8]; uint4 u; } H, L;
    #pragma unroll
    for (int j = 0; j < 8; ++j) {
        __nv_bfloat16 hh = __float2bfloat16(v[j]);
        H.bb[j] = hh;
        L.bb[j] = __float2bfloat16(v[j] - __bfloat162float(hh));
    }
    *(uint4*)(h + i) = H.u;
    *(uint4*)(l + i) = L.u;
}

// W [DM x 512] fp32 -> Wt hi/lo [512 x DM] bf16 (transposed, K-major)
__global__ void __launch_bounds__(256) splitw3_kernel(
    const float* __restrict__ W0, __nv_bfloat16* __restrict__ h0, __nv_bfloat16* __restrict__ l0,
    const float* __restrict__ W1, __nv_bfloat16* __restrict__ h1, __nv_bfloat16* __restrict__ l1,
    const float* __restrict__ W2, __nv_bfloat16* __restrict__ h2, __nv_bfloat16* __restrict__ l2)
{
    const float* W = (blockIdx.y == 0) ? W0 : (blockIdx.y == 1) ? W1 : W2;
    __nv_bfloat16* h = (blockIdx.y == 0) ? h0 : (blockIdx.y == 1) ? h1 : h2;
    __nv_bfloat16* l = (blockIdx.y == 0) ? l0 : (blockIdx.y == 1) ? l1 : l2;
    int o = blockIdx.x * 256 + threadIdx.x;   // o = n*DM + k, n<512
    int n = o >> 10, k = o & 1023;
    float v = W[(size_t)k * 512 + n];
    __nv_bfloat16 hh = __float2bfloat16(v);
    h[o] = hh;
    l[o] = __float2bfloat16(v - __bfloat162float(hh));
}

// ---------------------------------------------------------------------------
// fused mask + softmax reading fp32 scores, writing bf16 hi/lo probabilities
// ---------------------------------------------------------------------------
__global__ void __launch_bounds__(256) softmax_split(
    const float* __restrict__ S, __nv_bfloat16* __restrict__ Ph,
    __nv_bfloat16* __restrict__ Pl,
    const int* __restrict__ qpad, const int* __restrict__ kpad, float scale)
{
    const int r = blockIdx.x;
    const int b = r >> 11, i = r & (SS - 1);
    const float* row = S + (size_t)r * SS;
    const int* kp = kpad + b * SS;
    const bool qp = (qpad[r] != 0);
    const int tid = threadIdx.x, j0 = tid * 8;
    const int lane = tid & 31, warp = tid >> 5;

    float4 a = ((const float4*)(row + j0))[0];
    float4 c = ((const float4*)(row + j0))[1];
    int4 ka = ((const int4*)(kp + j0))[0];
    int4 kb = ((const int4*)(kp + j0))[1];
    float x[8] = {a.x, a.y, a.z, a.w, c.x, c.y, c.z, c.w};
    int km[8] = {ka.x, ka.y, ka.z, ka.w, kb.x, kb.y, kb.z, kb.w};

    float m = -INFINITY;
    #pragma unroll
    for (int u = 0; u < 8; ++u) {
        bool valid = (!qp) && (j0 + u <= i) && (km[u] == 0);
        x[u] = valid ? x[u] * scale : -INFINITY;
        m = fmaxf(m, x[u]);
    }

    __shared__ float redm[8], reds[8];
    #pragma unroll
    for (int o = 16; o; o >>= 1) m = fmaxf(m, __shfl_xor_sync(0xffffffffu, m, o));
    if (lane == 0) redm[warp] = m;
    __syncthreads();
    float bm = -INFINITY;
    #pragma unroll
    for (int w = 0; w < 8; ++w) bm = fmaxf(bm, redm[w]);

    uint4* oh = (uint4*)(Ph + (size_t)r * SS + j0);
    uint4* ol = (uint4*)(Pl + (size_t)r * SS + j0);

    if (bm == -INFINITY) {     // fully masked row -> zeros
        uint4 zz = make_uint4(0, 0, 0, 0);
        *oh = zz; *ol = zz;
        return;
    }

    float e[8];
    float s = 0.0f;
    #pragma unroll
    for (int u = 0; u < 8; ++u) {
        e[u] = (x[u] == -INFINITY) ? 0.0f : __expf(x[u] - bm);
        s += e[u];
    }
    #pragma unroll
    for (int o = 16; o; o >>= 1) s += __shfl_xor_sync(0xffffffffu, s, o);
    if (lane == 0) reds[warp] = s;
    __syncthreads();
    float bs = 0.0f;
    #pragma unroll
    for (int w = 0; w < 8; ++w) bs += reds[w];

    const float rinv = 1.0f / bs;
    union { __nv_bfloat16 bb[8]; uint4 u; } H, L;
    #pragma unroll
    for (int u = 0; u < 8; ++u) {
        float p = e[u] * rinv;
        __nv_bfloat16 hh = __float2bfloat16(p);
        H.bb[u] = hh;
        L.bb[u] = __float2bfloat16(p - __bfloat162float(hh));
    }
    *oh = H.u;
    *ol = L.u;
}

// ---------------------------------------------------------------------------
extern "C" void kernel_launch(void* const* d_in, const int* in_sizes, int n_in,
                              void* d_out, int out_size)
{
    const float* sq   = (const float*)d_in[0];
    const float* skv  = (const float*)d_in[1];
    const int*   qpad = (const int*)d_in[2];
    const int*   kpad = (const int*)d_in[3];
    const float* Wq   = (const float*)d_in[4];
    const float* Wk   = (const float*)d_in[5];
    const float* Wv   = (const float*)d_in[6];
    float* out = (float*)d_out;

    float *Sb;
    __nv_bfloat16 *sqh, *sql, *kvh, *kvl, *wqh, *wql, *wkh, *wkl, *wvh, *wvl;
    __nv_bfloat16 *vth, *vtl, *pH, *pL;
    __half *q16, *k16;
    cudaGetSymbolAddress((void**)&Sb,  g_S);
    cudaGetSymbolAddress((void**)&sqh, g_sqh); cudaGetSymbolAddress((void**)&sql, g_sql);
    cudaGetSymbolAddress((void**)&kvh, g_kvh); cudaGetSymbolAddress((void**)&kvl, g_kvl);
    cudaGetSymbolAddress((void**)&wqh, g_wqh); cudaGetSymbolAddress((void**)&wql, g_wql);
    cudaGetSymbolAddress((void**)&wkh, g_wkh); cudaGetSymbolAddress((void**)&wkl, g_wkl);
    cudaGetSymbolAddress((void**)&wvh, g_wvh); cudaGetSymbolAddress((void**)&wvl, g_wvl);
    cudaGetSymbolAddress((void**)&q16, g_q16); cudaGetSymbolAddress((void**)&k16, g_k16);
    cudaGetSymbolAddress((void**)&vth, g_vth); cudaGetSymbolAddress((void**)&vtl, g_vtl);
    cudaGetSymbolAddress((void**)&pH,  g_ph);  cudaGetSymbolAddress((void**)&pL,  g_pl);

    const int SMEMSZ = 98304;   // 3 x (16 KB A + 16 KB B)
    cudaFuncSetAttribute(proj3_kernel,
                         cudaFuncAttributeMaxDynamicSharedMemorySize, SMEMSZ);
    cudaFuncSetAttribute(scores_kernel,
                         cudaFuncAttributeMaxDynamicSharedMemorySize, SMEMSZ);
    cudaFuncSetAttribute(attnv_kernel,
                         cudaFuncAttributeMaxDynamicSharedMemorySize, SMEMSZ);

    // 1) split both sources to bf16 hi/lo (one launch)
    const int nsrc = MTOK * DM;                    // 16.7M
    split2_kernel<<<dim3(nsrc / 2048, 2), 256>>>(sq, sqh, sql, skv, kvh, kvl);
    // 2) split + transpose all weights (one launch)
    splitw3_kernel<<<dim3((DK * DM) / 256, 3), 256>>>(
        Wq, wqh, wql, Wk, wkh, wkl, Wv, wvh, wvl);

    // 3) all three projections in ONE launch (1536 CTAs); Q,K emitted fp16
    proj3_kernel<<<1536, 128, SMEMSZ>>>(
        sqh, sql, kvh, kvl, wqh, wql, wkh, wkl, wvh, wvl,
        q16, k16, vth, vtl);

    // 4) scores S_b = Q_b * K_b^T (1-term fp16, causal tile-skip), fp32 epilogue
    scores_kernel<<<dim3(SS / 128, SS / 128, BB), 128, SMEMSZ>>>(q16, k16, Sb);

    // 5) mask + softmax -> P hi/lo bf16
    const float scale = 0.04419417382415922f;   // 1/sqrt(512)
    softmax_split<<<MTOK, 256>>>(Sb, pH, pL, qpad, kpad, scale);

    // 6) O_b = P_b * V_b (K truncated at causal diagonal, longest-first order)
    attnv_kernel<<<dim3(DV / 128, SS / 128, BB), 128, SMEMSZ>>>(
        pH, pL, vth, vtl, out);
}

// round 13
// speedup vs baseline: 1.6399x; 1.2169x over previous
#include <cuda_runtime.h>
#include <cuda_bf16.h>
#include <cuda_fp16.h>
#include <stdint.h>
#include <math.h>

#define BB 8
#define SS 2048
#define DM 1024
#define DK 512
#define DV 512
#define MTOK (BB*SS)   // 16384

// ---------------- scratch (static device allocations) ----------------
__device__ __align__(256) float         g_S  [(size_t)BB*SS*SS];      // 134 MB scores
__device__ __align__(256) __nv_bfloat16 g_sqh[(size_t)MTOK*DM];
__device__ __align__(256) __nv_bfloat16 g_sql[(size_t)MTOK*DM];
__device__ __align__(256) __nv_bfloat16 g_kvh[(size_t)MTOK*DM];
__device__ __align__(256) __nv_bfloat16 g_kvl[(size_t)MTOK*DM];
__device__ __align__(256) __nv_bfloat16 g_wqh[(size_t)DK*DM];
__device__ __align__(256) __nv_bfloat16 g_wql[(size_t)DK*DM];
__device__ __align__(256) __nv_bfloat16 g_wkh[(size_t)DK*DM];
__device__ __align__(256) __nv_bfloat16 g_wkl[(size_t)DK*DM];
__device__ __align__(256) __nv_bfloat16 g_wvh[(size_t)DV*DM];
__device__ __align__(256) __nv_bfloat16 g_wvl[(size_t)DV*DM];
__device__ __align__(256) __half        g_q16[(size_t)MTOK*DK];       // Q fp16
__device__ __align__(256) __half        g_k16[(size_t)MTOK*DK];       // K fp16
__device__ __align__(256) __half        g_vt16[(size_t)DV*MTOK];     // V^T fp16: [512 x 16384]
__device__ __align__(256) __half        g_p16[(size_t)MTOK*SS];      // P fp16 (67 MB)

// ---------------- portable PTX helpers (sm_80+ only) ----------
__device__ __forceinline__ uint32_t s2u(const void* p) {
    return (uint32_t)__cvta_generic_to_shared(p);
}

#define CPA16(dst, src) \
    asm volatile("cp.async.cg.shared.global [%0], [%1], 16;" :: "r"(dst), "l"(src))

#define CPA_COMMIT() asm volatile("cp.async.commit_group;" ::: "memory")
#define CPA_WAIT0()  asm volatile("cp.async.wait_group 0;" ::: "memory")
#define CPA_WAIT1()  asm volatile("cp.async.wait_group 1;" ::: "memory")

#define LDSM_X4(r, addr) \
    asm volatile("ldmatrix.sync.aligned.m8n8.x4.shared.b16 {%0,%1,%2,%3}, [%4];" \
        : "=r"((r)[0]), "=r"((r)[1]), "=r"((r)[2]), "=r"((r)[3]) : "r"(addr))

#define MMA16816(d, a, b) \
    asm volatile("mma.sync.aligned.m16n8k16.row.col.f32.bf16.bf16.f32 " \
        "{%0,%1,%2,%3}, {%4,%5,%6,%7}, {%8,%9}, {%0,%1,%2,%3};" \
        : "+f"((d)[0]), "+f"((d)[1]), "+f"((d)[2]), "+f"((d)[3]) \
        : "r"((a)[0]), "r"((a)[1]), "r"((a)[2]), "r"((a)[3]), \
          "r"((b)[0]), "r"((b)[1]))

#define MMA16816H(d, a, b) \
    asm volatile("mma.sync.aligned.m16n8k16.row.col.f32.f16.f16.f32 " \
        "{%0,%1,%2,%3}, {%4,%5,%6,%7}, {%8,%9}, {%0,%1,%2,%3};" \
        : "+f"((d)[0]), "+f"((d)[1]), "+f"((d)[2]), "+f"((d)[3]) \
        : "r"((a)[0]), "r"((a)[1]), "r"((a)[2]), "r"((a)[3]), \
          "r"((b)[0]), "r"((b)[1]))

// ---------------------------------------------------------------------------
// Shared GEMM core.
//   NSEG==3: acc += A0*B0^T + A1*B0^T + A0*B1^T   (3-term bf16 split)
//   NSEG==1: acc += A0*B0^T                        (single term; F16H -> fp16 mma)
//   4 warps (2x2), warp tile 64x64, BK=64, 3-stage cp.async pipeline,
//   single-sync mainloop. Caller provides 96 KB dynamic smem.
//   Smem row = 64 elems = 128 B = 8 x 16B chunks; chunk c stored at c^(row&7).
//   KTRUNC: per-segment K truncated at bm0+128 (attn*V causal)
// Operand element size is 2 bytes (bf16 or fp16) — address math identical.
// ---------------------------------------------------------------------------
template <int NSEG, bool KTRUNC, bool F16H>
__device__ __forceinline__ void gemm_core(
    const __nv_bfloat16* __restrict__ A0, const __nv_bfloat16* __restrict__ A1,
    const __nv_bfloat16* __restrict__ B0, const __nv_bfloat16* __restrict__ B1,
    int bm0, int bn0, int segK, int ldA, int ldB,
    float acc[4][8][4])
{
    extern __shared__ char sm[];
    const uint32_t smb = s2u(sm);
    const uint32_t aBuf[3] = { smb,         smb + 32768, smb + 65536 };
    const uint32_t bBuf[3] = { smb + 16384, smb + 49152, smb + 81920 };

    const int tid = threadIdx.x, wid = tid >> 5, lane = tid & 31;
    const int warp_m = (wid >> 1) * 64;   // 0 or 64
    const int warp_n = (wid & 1) * 64;    // 0 or 64

    int kEnd = segK;
    if (KTRUNC) { int l = bm0 + 128; kEnd = (l < segK) ? l : segK; }
    const int cps   = kEnd >> 6;          // 64-elem chunks per segment
    const int total = NSEG * cps;

    auto load_chunk = [&](int c, int buf) {
        int seg = (NSEG == 1) ? 0 : (c / cps);
        int ck  = (NSEG == 1) ? c : (c - seg * cps);
        const __nv_bfloat16* Aseg = (seg == 1) ? A1 : A0;
        const __nv_bfloat16* Bseg = (seg == 2) ? B1 : B0;
        const __nv_bfloat16* gA = Aseg + (size_t)bm0 * ldA + (ck << 6);
        const __nv_bfloat16* gB = Bseg + (size_t)bn0 * ldB + (ck << 6);
        const uint32_t bA = aBuf[buf], bB = bBuf[buf];
        #pragma unroll
        for (int t = 0; t < 8; ++t) {
            int f = tid + t * 128;            // 0..1023
            int row = f >> 3, cch = f & 7;
            int sw = cch ^ (row & 7);
            CPA16(bA + row * 128 + sw * 16, (const char*)(gA + (size_t)row * ldA) + cch * 16);
            CPA16(bB + row * 128 + sw * 16, (const char*)(gB + (size_t)row * ldB) + cch * 16);
        }
        CPA_COMMIT();
    };

    load_chunk(0, 0);
    load_chunk(1, 1);
    CPA_WAIT1();
    __syncthreads();

    const int wi = lane & 7, g = lane >> 3;   // ldmatrix lane-group decomposition

    int buf = 0;
    for (int c = 0; c < total; ++c) {
        const uint32_t bA = aBuf[buf], bB = bBuf[buf];
        int nb = buf + 2; if (nb >= 3) nb -= 3;

        #pragma unroll
        for (int ks = 0; ks < 4; ++ks) {
            if (ks == 1 && c + 2 < total) load_chunk(c + 2, nb);

            uint32_t a[4][4];
            #pragma unroll
            for (int mf = 0; mf < 4; ++mf) {
                int row = warp_m + mf * 16 + (g & 1) * 8 + wi;
                int cch = 2 * ks + (g >> 1);
                LDSM_X4(a[mf], bA + row * 128 + (cch ^ (row & 7)) * 16);
            }
            uint32_t b[8][2];
            #pragma unroll
            for (int p = 0; p < 4; ++p) {
                uint32_t r[4];
                int row = warp_n + p * 16 + (g >> 1) * 8 + wi;
                int cch = 2 * ks + (g & 1);
                LDSM_X4(r, bB + row * 128 + (cch ^ (row & 7)) * 16);
                b[2 * p + 0][0] = r[0]; b[2 * p + 0][1] = r[1];
                b[2 * p + 1][0] = r[2]; b[2 * p + 1][1] = r[3];
            }
            #pragma unroll
            for (int mf = 0; mf < 4; ++mf)
                #pragma unroll
                for (int nf = 0; nf < 8; ++nf) {
                    if (F16H) { MMA16816H(acc[mf][nf], a[mf], b[nf]); }
                    else      { MMA16816 (acc[mf][nf], a[mf], b[nf]); }
                }
        }

        if (c + 1 < total) {
            if (c + 2 < total) { CPA_WAIT1(); } else { CPA_WAIT0(); }
            __syncthreads();
        }
        if (++buf == 3) buf = 0;
    }
}

// epilogue: fp32 store. c-frag map: c0,c1 -> (lane/4, (lane%4)*2), c2,c3 -> row+8
__device__ __forceinline__ void epi_f32(
    float acc[4][8][4], float* __restrict__ Cf, int bm0, int bn0, int ldC)
{
    const int tid = threadIdx.x, wid = tid >> 5, lane = tid & 31;
    const int warp_m = (wid >> 1) * 64, warp_n = (wid & 1) * 64;
    const int rq = lane >> 2, cq = (lane & 3) * 2;
    #pragma unroll
    for (int mf = 0; mf < 4; ++mf)
        #pragma unroll
        for (int nf = 0; nf < 8; ++nf) {
            int m0 = bm0 + warp_m + mf * 16 + rq;
            int n0 = bn0 + warp_n + nf * 8 + cq;
            *(float2*)(Cf + (size_t)m0 * ldC + n0) =
                make_float2(acc[mf][nf][0], acc[mf][nf][1]);
            *(float2*)(Cf + (size_t)(m0 + 8) * ldC + n0) =
                make_float2(acc[mf][nf][2], acc[mf][nf][3]);
        }
}

// epilogue: single fp16 store
__device__ __forceinline__ void epi_f16(
    float acc[4][8][4], __half* __restrict__ C, int bm0, int bn0, int ldC)
{
    const int tid = threadIdx.x, wid = tid >> 5, lane = tid & 31;
    const int warp_m = (wid >> 1) * 64, warp_n = (wid & 1) * 64;
    const int rq = lane >> 2, cq = (lane & 3) * 2;
    #pragma unroll
    for (int mf = 0; mf < 4; ++mf)
        #pragma unroll
        for (int nf = 0; nf < 8; ++nf) {
            int m0 = bm0 + warp_m + mf * 16 + rq;
            int n0 = bn0 + warp_n + nf * 8 + cq;
            #pragma unroll
            for (int h = 0; h < 2; ++h) {
                __half2 v = __floats2half2_rn(acc[mf][nf][2 * h + 0],
                                              acc[mf][nf][2 * h + 1]);
                *(__half2*)(C + (size_t)(m0 + 8 * h) * ldC + n0) = v;
            }
        }
}

// ---------------------------------------------------------------------------
// All three projections in ONE launch (1536 CTAs).
// blockIdx.x: [0,512) -> Q (fp16), [512,1024) -> K (fp16), [1024,1536) -> Vt (fp16)
// All use 3-term bf16 GEMM internally (full precision accumulate).
// ---------------------------------------------------------------------------
__global__ void __launch_bounds__(128, 2) proj3_kernel(
    const __nv_bfloat16* __restrict__ sqh, const __nv_bfloat16* __restrict__ sql,
    const __nv_bfloat16* __restrict__ kvh, const __nv_bfloat16* __restrict__ kvl,
    const __nv_bfloat16* __restrict__ wqh, const __nv_bfloat16* __restrict__ wql,
    const __nv_bfloat16* __restrict__ wkh, const __nv_bfloat16* __restrict__ wkl,
    const __nv_bfloat16* __restrict__ wvh, const __nv_bfloat16* __restrict__ wvl,
    __half* __restrict__ q16, __half* __restrict__ k16,
    __half* __restrict__ vt16)
{
    const int bx = blockIdx.x;
    const int p = bx >> 9;        // 0,1,2
    const int t = bx & 511;
    float acc[4][8][4] = {};
    if (p == 0) {
        int bm0 = (t >> 2) * 128, bn0 = (t & 3) * 128;
        gemm_core<3, false, false>(sqh, sql, wqh, wql, bm0, bn0, DM, DM, DM, acc);
        epi_f16(acc, q16, bm0, bn0, DK);
    } else if (p == 1) {
        int bm0 = (t >> 2) * 128, bn0 = (t & 3) * 128;
        gemm_core<3, false, false>(kvh, kvl, wkh, wkl, bm0, bn0, DM, DM, DM, acc);
        epi_f16(acc, k16, bm0, bn0, DK);
    } else {
        int bm0 = (t & 3) * 128, bn0 = (t >> 2) * 128;
        gemm_core<3, false, false>(wvh, wvl, kvh, kvl, bm0, bn0, DM, DM, DM, acc);
        epi_f16(acc, vt16, bm0, bn0, MTOK);
    }
}

// ---------------------------------------------------------------------------
// Scores: S_b = Q_b * K_b^T, 1-term fp16, causal tile-skip, fp32 epilogue
// ---------------------------------------------------------------------------
__global__ void __launch_bounds__(128, 2) scores_kernel(
    const __half* __restrict__ q16, const __half* __restrict__ k16,
    float* __restrict__ Sb)
{
    const int bn0 = blockIdx.x * 128;
    const int bm0 = blockIdx.y * 128;
    if (bn0 >= bm0 + 128) return;    // above causal diagonal
    const long long z = blockIdx.z;
    const long long soff = z * (long long)SS * DK;
    float acc[4][8][4] = {};
    gemm_core<1, false, true>(
        (const __nv_bfloat16*)(q16 + soff), nullptr,
        (const __nv_bfloat16*)(k16 + soff), nullptr,
        bm0, bn0, DK, DK, DK, acc);
    epi_f32(acc, Sb + z * (long long)SS * SS, bm0, bn0, SS);
}

// ---------------------------------------------------------------------------
// attn*V: O_b = P_b * V_b, 1-term fp16, K truncated at causal diagonal.
// bm order REVERSED (longest-work CTAs first).
// ---------------------------------------------------------------------------
__global__ void __launch_bounds__(128, 2) attnv_kernel(
    const __half* __restrict__ p16, const __half* __restrict__ vt16,
    float* __restrict__ out)
{
    const int bn0 = blockIdx.x * 128;
    const int bm0 = (gridDim.y - 1 - blockIdx.y) * 128;   // longest first
    const long long z = blockIdx.z;
    float acc[4][8][4] = {};
    gemm_core<1, true, true>(
        (const __nv_bfloat16*)(p16 + z * (long long)SS * SS), nullptr,
        (const __nv_bfloat16*)(vt16 + z * (long long)SS),     nullptr,
        bm0, bn0, SS, SS, MTOK, acc);
    epi_f32(acc, out + z * (long long)SS * DV, bm0, bn0, DV);
}

// ---------------------------------------------------------------------------
// fp32 -> bf16 (hi, lo) split for both sources in one launch (grid.y selects)
// ---------------------------------------------------------------------------
__global__ void __launch_bounds__(256) split2_kernel(
    const float* __restrict__ x0, __nv_bfloat16* __restrict__ h0, __nv_bfloat16* __restrict__ l0,
    const float* __restrict__ x1, __nv_bfloat16* __restrict__ h1, __nv_bfloat16* __restrict__ l1)
{
    const float* x = blockIdx.y ? x1 : x0;
    __nv_bfloat16* h = blockIdx.y ? h1 : h0;
    __nv_bfloat16* l = blockIdx.y ? l1 : l0;
    int i = (blockIdx.x * 256 + threadIdx.x) * 8;
    float4 a = *(const float4*)(x + i);
    float4 b = *(const float4*)(x + i + 4);
    float v[8] = {a.x, a.y, a.z, a.w, b.x, b.y, b.z, b.w};
    union { __nv_bfloat16 bb[8]; uint4 u; } H, L;
    #pragma unroll
    for (int j = 0; j < 8; ++j) {
        __nv_bfloat16 hh = __float2bfloat16(v[j]);
        H.bb[j] = hh;
        L.bb[j] = __float2bfloat16(v[j] - __bfloat162float(hh));
    }
    *(uint4*)(h + i) = H.u;
    *(uint4*)(l + i) = L.u;
}

// W [DM x 512] fp32 -> Wt hi/lo [512 x DM] bf16 (transposed, K-major)
__global__ void __launch_bounds__(256) splitw3_kernel(
    const float* __restrict__ W0, __nv_bfloat16* __restrict__ h0, __nv_bfloat16* __restrict__ l0,
    const float* __restrict__ W1, __nv_bfloat16* __restrict__ h1, __nv_bfloat16* __restrict__ l1,
    const float* __restrict__ W2, __nv_bfloat16* __restrict__ h2, __nv_bfloat16* __restrict__ l2)
{
    const float* W = (blockIdx.y == 0) ? W0 : (blockIdx.y == 1) ? W1 : W2;
    __nv_bfloat16* h = (blockIdx.y == 0) ? h0 : (blockIdx.y == 1) ? h1 : h2;
    __nv_bfloat16* l = (blockIdx.y == 0) ? l0 : (blockIdx.y == 1) ? l1 : l2;
    int o = blockIdx.x * 256 + threadIdx.x;   // o = n*DM + k, n<512
    int n = o >> 10, k = o & 1023;
    float v = W[(size_t)k * 512 + n];
    __nv_bfloat16 hh = __float2bfloat16(v);
    h[o] = hh;
    l[o] = __float2bfloat16(v - __bfloat162float(hh));
}

// ---------------------------------------------------------------------------
// fused mask + softmax reading fp32 scores, writing fp16 probabilities
// ---------------------------------------------------------------------------
__global__ void __launch_bounds__(256) softmax_f16(
    const float* __restrict__ S, __half* __restrict__ P,
    const int* __restrict__ qpad, const int* __restrict__ kpad, float scale)
{
    const int r = blockIdx.x;
    const int b = r >> 11, i = r & (SS - 1);
    const float* row = S + (size_t)r * SS;
    const int* kp = kpad + b * SS;
    const bool qp = (qpad[r] != 0);
    const int tid = threadIdx.x, j0 = tid * 8;
    const int lane = tid & 31, warp = tid >> 5;

    float4 a = ((const float4*)(row + j0))[0];
    float4 c = ((const float4*)(row + j0))[1];
    int4 ka = ((const int4*)(kp + j0))[0];
    int4 kb = ((const int4*)(kp + j0))[1];
    float x[8] = {a.x, a.y, a.z, a.w, c.x, c.y, c.z, c.w};
    int km[8] = {ka.x, ka.y, ka.z, ka.w, kb.x, kb.y, kb.z, kb.w};

    float m = -INFINITY;
    #pragma unroll
    for (int u = 0; u < 8; ++u) {
        bool valid = (!qp) && (j0 + u <= i) && (km[u] == 0);
        x[u] = valid ? x[u] * scale : -INFINITY;
        m = fmaxf(m, x[u]);
    }

    __shared__ float redm[8], reds[8];
    #pragma unroll
    for (int o = 16; o; o >>= 1) m = fmaxf(m, __shfl_xor_sync(0xffffffffu, m, o));
    if (lane == 0) redm[warp] = m;
    __syncthreads();
    float bm = -INFINITY;
    #pragma unroll
    for (int w = 0; w < 8; ++w) bm = fmaxf(bm, redm[w]);

    uint4* op = (uint4*)(P + (size_t)r * SS + j0);

    if (bm == -INFINITY) {     // fully masked row -> zeros
        *op = make_uint4(0, 0, 0, 0);
        return;
    }

    float e[8];
    float s = 0.0f;
    #pragma unroll
    for (int u = 0; u < 8; ++u) {
        e[u] = (x[u] == -INFINITY) ? 0.0f : __expf(x[u] - bm);
        s += e[u];
    }
    #pragma unroll
    for (int o = 16; o; o >>= 1) s += __shfl_xor_sync(0xffffffffu, s, o);
    if (lane == 0) reds[warp] = s;
    __syncthreads();
    float bs = 0.0f;
    #pragma unroll
    for (int w = 0; w < 8; ++w) bs += reds[w];

    const float rinv = 1.0f / bs;
    union { __half2 hh[4]; uint4 u; } O;
    #pragma unroll
    for (int u = 0; u < 4; ++u)
        O.hh[u] = __floats2half2_rn(e[2 * u] * rinv, e[2 * u + 1] * rinv);
    *op = O.u;
}

// ---------------------------------------------------------------------------
extern "C" void kernel_launch(void* const* d_in, const int* in_sizes, int n_in,
                              void* d_out, int out_size)
{
    const float* sq   = (const float*)d_in[0];
    const float* skv  = (const float*)d_in[1];
    const int*   qpad = (const int*)d_in[2];
    const int*   kpad = (const int*)d_in[3];
    const float* Wq   = (const float*)d_in[4];
    const float* Wk   = (const float*)d_in[5];
    const float* Wv   = (const float*)d_in[6];
    float* out = (float*)d_out;

    float *Sb;
    __nv_bfloat16 *sqh, *sql, *kvh, *kvl, *wqh, *wql, *wkh, *wkl, *wvh, *wvl;
    __half *q16, *k16, *vt16, *p16;
    cudaGetSymbolAddress((void**)&Sb,  g_S);
    cudaGetSymbolAddress((void**)&sqh, g_sqh); cudaGetSymbolAddress((void**)&sql, g_sql);
    cudaGetSymbolAddress((void**)&kvh, g_kvh); cudaGetSymbolAddress((void**)&kvl, g_kvl);
    cudaGetSymbolAddress((void**)&wqh, g_wqh); cudaGetSymbolAddress((void**)&wql, g_wql);
    cudaGetSymbolAddress((void**)&wkh, g_wkh); cudaGetSymbolAddress((void**)&wkl, g_wkl);
    cudaGetSymbolAddress((void**)&wvh, g_wvh); cudaGetSymbolAddress((void**)&wvl, g_wvl);
    cudaGetSymbolAddress((void**)&q16, g_q16); cudaGetSymbolAddress((void**)&k16, g_k16);
    cudaGetSymbolAddress((void**)&vt16, g_vt16);
    cudaGetSymbolAddress((void**)&p16,  g_p16);

    const int SMEMSZ = 98304;   // 3 x (16 KB A + 16 KB B)
    cudaFuncSetAttribute(proj3_kernel,
                         cudaFuncAttributeMaxDynamicSharedMemorySize, SMEMSZ);
    cudaFuncSetAttribute(scores_kernel,
                         cudaFuncAttributeMaxDynamicSharedMemorySize, SMEMSZ);
    cudaFuncSetAttribute(attnv_kernel,
                         cudaFuncAttributeMaxDynamicSharedMemorySize, SMEMSZ);

    // 1) split both sources to bf16 hi/lo (one launch)
    const int nsrc = MTOK * DM;                    // 16.7M
    split2_kernel<<<dim3(nsrc / 2048, 2), 256>>>(sq, sqh, sql, skv, kvh, kvl);
    // 2) split + transpose all weights (one launch)
    splitw3_kernel<<<dim3((DK * DM) / 256, 3), 256>>>(
        Wq, wqh, wql, Wk, wkh, wkl, Wv, wvh, wvl);

    // 3) all three projections in ONE launch (1536 CTAs); Q,K,Vt emitted fp16
    proj3_kernel<<<1536, 128, SMEMSZ>>>(
        sqh, sql, kvh, kvl, wqh, wql, wkh, wkl, wvh, wvl,
        q16, k16, vt16);

    // 4) scores S_b = Q_b * K_b^T (1-term fp16, causal tile-skip), fp32 epilogue
    scores_kernel<<<dim3(SS / 128, SS / 128, BB), 128, SMEMSZ>>>(q16, k16, Sb);

    // 5) mask + softmax -> P fp16
    const float scale = 0.04419417382415922f;   // 1/sqrt(512)
    softmax_f16<<<MTOK, 256>>>(Sb, p16, qpad, kpad, scale);

    // 6) O_b = P_b * V_b (1-term fp16, K truncated at causal diagonal,
    //    longest-first order)
    attnv_kernel<<<dim3(DV / 128, SS / 128, BB), 128, SMEMSZ>>>(
        p16, vt16, out);
}

// round 14
// speedup vs baseline: 2.0772x; 1.2667x over previous
#include <cuda_runtime.h>
#include <cuda_bf16.h>
#include <cuda_fp16.h>
#include <stdint.h>
#include <math.h>

#define BB 8
#define SS 2048
#define DM 1024
#define DK 512
#define DV 512
#define MTOK (BB*SS)   // 16384

// ---------------- scratch (static device allocations) ----------------
__device__ __align__(256) float  g_S   [(size_t)BB*SS*SS];    // 134 MB scores
__device__ __align__(256) __half g_sqh [(size_t)MTOK*DM];     // sq fp16 hi
__device__ __align__(256) __half g_sql [(size_t)MTOK*DM];     // sq fp16 lo
__device__ __align__(256) __half g_kvh [(size_t)MTOK*DM];     // kv fp16 hi (also single-fp16 kv)
__device__ __align__(256) __half g_kvl [(size_t)MTOK*DM];     // kv fp16 lo
__device__ __align__(256) __half g_wq16[(size_t)DK*DM];       // Wq^T single fp16
__device__ __align__(256) __half g_wk16[(size_t)DK*DM];       // Wk^T single fp16
__device__ __align__(256) __half g_wvh [(size_t)DV*DM];       // Wv^T fp16 hi
__device__ __align__(256) __half g_wvl [(size_t)DV*DM];       // Wv^T fp16 lo
__device__ __align__(256) __half g_q16 [(size_t)MTOK*DK];     // Q fp16
__device__ __align__(256) __half g_k16 [(size_t)MTOK*DK];     // K fp16
__device__ __align__(256) __half g_vt16[(size_t)DV*MTOK];     // V^T fp16 [512 x 16384]
__device__ __align__(256) __half g_p16 [(size_t)MTOK*SS];     // P fp16 (67 MB)

// ---------------- portable PTX helpers (sm_80+ only) ----------
__device__ __forceinline__ uint32_t s2u(const void* p) {
    return (uint32_t)__cvta_generic_to_shared(p);
}

#define CPA16(dst, src) \
    asm volatile("cp.async.cg.shared.global [%0], [%1], 16;" :: "r"(dst), "l"(src))

#define CPA_COMMIT() asm volatile("cp.async.commit_group;" ::: "memory")
#define CPA_WAIT0()  asm volatile("cp.async.wait_group 0;" ::: "memory")
#define CPA_WAIT1()  asm volatile("cp.async.wait_group 1;" ::: "memory")

#define LDSM_X4(r, addr) \
    asm volatile("ldmatrix.sync.aligned.m8n8.x4.shared.b16 {%0,%1,%2,%3}, [%4];" \
        : "=r"((r)[0]), "=r"((r)[1]), "=r"((r)[2]), "=r"((r)[3]) : "r"(addr))

#define MMA16816H(d, a, b) \
    asm volatile("mma.sync.aligned.m16n8k16.row.col.f32.f16.f16.f32 " \
        "{%0,%1,%2,%3}, {%4,%5,%6,%7}, {%8,%9}, {%0,%1,%2,%3};" \
        : "+f"((d)[0]), "+f"((d)[1]), "+f"((d)[2]), "+f"((d)[3]) \
        : "r"((a)[0]), "r"((a)[1]), "r"((a)[2]), "r"((a)[3]), \
          "r"((b)[0]), "r"((b)[1]))

// ---------------------------------------------------------------------------
// Shared fp16 GEMM core.
//   NSEG==2: acc += A0*B0^T + A1*B0^T   (A exact via hi/lo split, B quantized)
//   NSEG==1: acc += A0*B0^T
//   4 warps (2x2), warp tile 64x64, BK=64, 3-stage cp.async pipeline,
//   single-sync mainloop. Caller provides 96 KB dynamic smem.
//   Smem row = 64 elems = 128 B = 8 x 16B chunks; chunk c stored at c^(row&7).
//   KTRUNC: per-segment K truncated at bm0+128 (attn*V causal)
// ---------------------------------------------------------------------------
template <int NSEG, bool KTRUNC>
__device__ __forceinline__ void gemm_core(
    const __half* __restrict__ A0, const __half* __restrict__ A1,
    const __half* __restrict__ B0,
    int bm0, int bn0, int segK, int ldA, int ldB,
    float acc[4][8][4])
{
    extern __shared__ char sm[];
    const uint32_t smb = s2u(sm);
    const uint32_t aBuf[3] = { smb,         smb + 32768, smb + 65536 };
    const uint32_t bBuf[3] = { smb + 16384, smb + 49152, smb + 81920 };

    const int tid = threadIdx.x, wid = tid >> 5, lane = tid & 31;
    const int warp_m = (wid >> 1) * 64;   // 0 or 64
    const int warp_n = (wid & 1) * 64;    // 0 or 64

    int kEnd = segK;
    if (KTRUNC) { int l = bm0 + 128; kEnd = (l < segK) ? l : segK; }
    const int cps   = kEnd >> 6;          // 64-elem chunks per segment
    const int total = NSEG * cps;

    auto load_chunk = [&](int c, int buf) {
        int seg = (NSEG == 1) ? 0 : (c / cps);
        int ck  = (NSEG == 1) ? c : (c - seg * cps);
        const __half* Aseg = (seg == 1) ? A1 : A0;
        const __half* gA = Aseg + (size_t)bm0 * ldA + (ck << 6);
        const __half* gB = B0   + (size_t)bn0 * ldB + (ck << 6);
        const uint32_t bA = aBuf[buf], bB = bBuf[buf];
        #pragma unroll
        for (int t = 0; t < 8; ++t) {
            int f = tid + t * 128;            // 0..1023
            int row = f >> 3, cch = f & 7;
            int sw = cch ^ (row & 7);
            CPA16(bA + row * 128 + sw * 16, (const char*)(gA + (size_t)row * ldA) + cch * 16);
            CPA16(bB + row * 128 + sw * 16, (const char*)(gB + (size_t)row * ldB) + cch * 16);
        }
        CPA_COMMIT();
    };

    load_chunk(0, 0);
    load_chunk(1, 1);
    CPA_WAIT1();
    __syncthreads();

    const int wi = lane & 7, g = lane >> 3;   // ldmatrix lane-group decomposition

    int buf = 0;
    for (int c = 0; c < total; ++c) {
        const uint32_t bA = aBuf[buf], bB = bBuf[buf];
        int nb = buf + 2; if (nb >= 3) nb -= 3;

        #pragma unroll
        for (int ks = 0; ks < 4; ++ks) {
            if (ks == 1 && c + 2 < total) load_chunk(c + 2, nb);

            uint32_t a[4][4];
            #pragma unroll
            for (int mf = 0; mf < 4; ++mf) {
                int row = warp_m + mf * 16 + (g & 1) * 8 + wi;
                int cch = 2 * ks + (g >> 1);
                LDSM_X4(a[mf], bA + row * 128 + (cch ^ (row & 7)) * 16);
            }
            uint32_t b[8][2];
            #pragma unroll
            for (int p = 0; p < 4; ++p) {
                uint32_t r[4];
                int row = warp_n + p * 16 + (g >> 1) * 8 + wi;
                int cch = 2 * ks + (g & 1);
                LDSM_X4(r, bB + row * 128 + (cch ^ (row & 7)) * 16);
                b[2 * p + 0][0] = r[0]; b[2 * p + 0][1] = r[1];
                b[2 * p + 1][0] = r[2]; b[2 * p + 1][1] = r[3];
            }
            #pragma unroll
            for (int mf = 0; mf < 4; ++mf)
                #pragma unroll
                for (int nf = 0; nf < 8; ++nf)
                    MMA16816H(acc[mf][nf], a[mf], b[nf]);
        }

        if (c + 1 < total) {
            if (c + 2 < total) { CPA_WAIT1(); } else { CPA_WAIT0(); }
            __syncthreads();
        }
        if (++buf == 3) buf = 0;
    }
}

// epilogue: fp32 store. c-frag map: c0,c1 -> (lane/4, (lane%4)*2), c2,c3 -> row+8
__device__ __forceinline__ void epi_f32(
    float acc[4][8][4], float* __restrict__ Cf, int bm0, int bn0, int ldC)
{
    const int tid = threadIdx.x, wid = tid >> 5, lane = tid & 31;
    const int warp_m = (wid >> 1) * 64, warp_n = (wid & 1) * 64;
    const int rq = lane >> 2, cq = (lane & 3) * 2;
    #pragma unroll
    for (int mf = 0; mf < 4; ++mf)
        #pragma unroll
        for (int nf = 0; nf < 8; ++nf) {
            int m0 = bm0 + warp_m + mf * 16 + rq;
            int n0 = bn0 + warp_n + nf * 8 + cq;
            *(float2*)(Cf + (size_t)m0 * ldC + n0) =
                make_float2(acc[mf][nf][0], acc[mf][nf][1]);
            *(float2*)(Cf + (size_t)(m0 + 8) * ldC + n0) =
                make_float2(acc[mf][nf][2], acc[mf][nf][3]);
        }
}

// epilogue: single fp16 store
__device__ __forceinline__ void epi_f16(
    float acc[4][8][4], __half* __restrict__ C, int bm0, int bn0, int ldC)
{
    const int tid = threadIdx.x, wid = tid >> 5, lane = tid & 31;
    const int warp_m = (wid >> 1) * 64, warp_n = (wid & 1) * 64;
    const int rq = lane >> 2, cq = (lane & 3) * 2;
    #pragma unroll
    for (int mf = 0; mf < 4; ++mf)
        #pragma unroll
        for (int nf = 0; nf < 8; ++nf) {
            int m0 = bm0 + warp_m + mf * 16 + rq;
            int n0 = bn0 + warp_n + nf * 8 + cq;
            #pragma unroll
            for (int h = 0; h < 2; ++h) {
                __half2 v = __floats2half2_rn(acc[mf][nf][2 * h + 0],
                                              acc[mf][nf][2 * h + 1]);
                *(__half2*)(C + (size_t)(m0 + 8 * h) * ldC + n0) = v;
            }
        }
}

// ---------------------------------------------------------------------------
// All three projections in ONE launch (1536 CTAs), all 2-segment fp16:
//   Q : A = sq hi/lo,  B = Wq^T single     -> fp16 out
//   K : A = kv hi/lo,  B = Wk^T single     -> fp16 out
//   Vt: A = Wv^T hi/lo, B = kv hi (single) -> fp16 out (produced transposed)
// blockIdx.x: [0,512) -> Q, [512,1024) -> K, [1024,1536) -> Vt
// ---------------------------------------------------------------------------
__global__ void __launch_bounds__(128, 2) proj3_kernel(
    const __half* __restrict__ sqh, const __half* __restrict__ sql,
    const __half* __restrict__ kvh, const __half* __restrict__ kvl,
    const __half* __restrict__ wq16, const __half* __restrict__ wk16,
    const __half* __restrict__ wvh, const __half* __restrict__ wvl,
    __half* __restrict__ q16, __half* __restrict__ k16,
    __half* __restrict__ vt16)
{
    const int bx = blockIdx.x;
    const int p = bx >> 9;        // 0,1,2
    const int t = bx & 511;
    float acc[4][8][4] = {};
    if (p == 0) {
        int bm0 = (t >> 2) * 128, bn0 = (t & 3) * 128;
        gemm_core<2, false>(sqh, sql, wq16, bm0, bn0, DM, DM, DM, acc);
        epi_f16(acc, q16, bm0, bn0, DK);
    } else if (p == 1) {
        int bm0 = (t >> 2) * 128, bn0 = (t & 3) * 128;
        gemm_core<2, false>(kvh, kvl, wk16, bm0, bn0, DM, DM, DM, acc);
        epi_f16(acc, k16, bm0, bn0, DK);
    } else {
        int bm0 = (t & 3) * 128, bn0 = (t >> 2) * 128;
        gemm_core<2, false>(wvh, wvl, kvh, bm0, bn0, DM, DM, DM, acc);
        epi_f16(acc, vt16, bm0, bn0, MTOK);
    }
}

// ---------------------------------------------------------------------------
// Scores: S_b = Q_b * K_b^T, 1-term fp16, causal tile-skip, fp32 epilogue
// ---------------------------------------------------------------------------
__global__ void __launch_bounds__(128, 2) scores_kernel(
    const __half* __restrict__ q16, const __half* __restrict__ k16,
    float* __restrict__ Sb)
{
    const int bn0 = blockIdx.x * 128;
    const int bm0 = blockIdx.y * 128;
    if (bn0 >= bm0 + 128) return;    // above causal diagonal
    const long long z = blockIdx.z;
    const long long soff = z * (long long)SS * DK;
    float acc[4][8][4] = {};
    gemm_core<1, false>(q16 + soff, nullptr, k16 + soff,
                        bm0, bn0, DK, DK, DK, acc);
    epi_f32(acc, Sb + z * (long long)SS * SS, bm0, bn0, SS);
}

// ---------------------------------------------------------------------------
// attn*V: O_b = P_b * V_b, 1-term fp16, K truncated at causal diagonal.
// bm order REVERSED (longest-work CTAs first).
// ---------------------------------------------------------------------------
__global__ void __launch_bounds__(128, 2) attnv_kernel(
    const __half* __restrict__ p16, const __half* __restrict__ vt16,
    float* __restrict__ out)
{
    const int bn0 = blockIdx.x * 128;
    const int bm0 = (gridDim.y - 1 - blockIdx.y) * 128;   // longest first
    const long long z = blockIdx.z;
    float acc[4][8][4] = {};
    gemm_core<1, true>(p16 + z * (long long)SS * SS, nullptr,
                       vt16 + z * (long long)SS,
                       bm0, bn0, SS, SS, MTOK, acc);
    epi_f32(acc, out + z * (long long)SS * DV, bm0, bn0, DV);
}

// ---------------------------------------------------------------------------
// fp32 -> fp16 (hi, lo) split for both sources in one launch (grid.y selects)
// ---------------------------------------------------------------------------
__global__ void __launch_bounds__(256) split2_kernel(
    const float* __restrict__ x0, __half* __restrict__ h0, __half* __restrict__ l0,
    const float* __restrict__ x1, __half* __restrict__ h1, __half* __restrict__ l1)
{
    const float* x = blockIdx.y ? x1 : x0;
    __half* h = blockIdx.y ? h1 : h0;
    __half* l = blockIdx.y ? l1 : l0;
    int i = (blockIdx.x * 256 + threadIdx.x) * 8;
    float4 a = *(const float4*)(x + i);
    float4 b = *(const float4*)(x + i + 4);
    float v[8] = {a.x, a.y, a.z, a.w, b.x, b.y, b.z, b.w};
    union { __half hh[8]; uint4 u; } H, L;
    #pragma unroll
    for (int j = 0; j < 8; ++j) {
        __half hv = __float2half_rn(v[j]);
        H.hh[j] = hv;
        L.hh[j] = __float2half_rn(v[j] - __half2float(hv));
    }
    *(uint4*)(h + i) = H.u;
    *(uint4*)(l + i) = L.u;
}

// Weights fp32 [DM x 512] -> transposed fp16 [512 x DM].
// grid.y: 0 -> Wq single, 1 -> Wk single, 2 -> Wv hi/lo
__global__ void __launch_bounds__(256) splitw3_kernel(
    const float* __restrict__ W0, __half* __restrict__ o0,
    const float* __restrict__ W1, __half* __restrict__ o1,
    const float* __restrict__ W2, __half* __restrict__ h2, __half* __restrict__ l2)
{
    int o = blockIdx.x * 256 + threadIdx.x;   // o = n*DM + k, n<512
    int n = o >> 10, k = o & 1023;
    if (blockIdx.y == 0) {
        o0[o] = __float2half_rn(W0[(size_t)k * 512 + n]);
    } else if (blockIdx.y == 1) {
        o1[o] = __float2half_rn(W1[(size_t)k * 512 + n]);
    } else {
        float v = W2[(size_t)k * 512 + n];
        __half hv = __float2half_rn(v);
        h2[o] = hv;
        l2[o] = __float2half_rn(v - __half2float(hv));
    }
}

// ---------------------------------------------------------------------------
// fused mask + softmax reading fp32 scores, writing fp16 probabilities
// ---------------------------------------------------------------------------
__global__ void __launch_bounds__(256) softmax_f16(
    const float* __restrict__ S, __half* __restrict__ P,
    const int* __restrict__ qpad, const int* __restrict__ kpad, float scale)
{
    const int r = blockIdx.x;
    const int b = r >> 11, i = r & (SS - 1);
    const float* row = S + (size_t)r * SS;
    const int* kp = kpad + b * SS;
    const bool qp = (qpad[r] != 0);
    const int tid = threadIdx.x, j0 = tid * 8;
    const int lane = tid & 31, warp = tid >> 5;

    float4 a = ((const float4*)(row + j0))[0];
    float4 c = ((const float4*)(row + j0))[1];
    int4 ka = ((const int4*)(kp + j0))[0];
    int4 kb = ((const int4*)(kp + j0))[1];
    float x[8] = {a.x, a.y, a.z, a.w, c.x, c.y, c.z, c.w};
    int km[8] = {ka.x, ka.y, ka.z, ka.w, kb.x, kb.y, kb.z, kb.w};

    float m = -INFINITY;
    #pragma unroll
    for (int u = 0; u < 8; ++u) {
        bool valid = (!qp) && (j0 + u <= i) && (km[u] == 0);
        x[u] = valid ? x[u] * scale : -INFINITY;
        m = fmaxf(m, x[u]);
    }

    __shared__ float redm[8], reds[8];
    #pragma unroll
    for (int o = 16; o; o >>= 1) m = fmaxf(m, __shfl_xor_sync(0xffffffffu, m, o));
    if (lane == 0) redm[warp] = m;
    __syncthreads();
    float bm = -INFINITY;
    #pragma unroll
    for (int w = 0; w < 8; ++w) bm = fmaxf(bm, redm[w]);

    uint4* op = (uint4*)(P + (size_t)r * SS + j0);

    if (bm == -INFINITY) {     // fully masked row -> zeros
        *op = make_uint4(0, 0, 0, 0);
        return;
    }

    float e[8];
    float s = 0.0f;
    #pragma unroll
    for (int u = 0; u < 8; ++u) {
        e[u] = (x[u] == -INFINITY) ? 0.0f : __expf(x[u] - bm);
        s += e[u];
    }
    #pragma unroll
    for (int o = 16; o; o >>= 1) s += __shfl_xor_sync(0xffffffffu, s, o);
    if (lane == 0) reds[warp] = s;
    __syncthreads();
    float bs = 0.0f;
    #pragma unroll
    for (int w = 0; w < 8; ++w) bs += reds[w];

    const float rinv = 1.0f / bs;
    union { __half2 hh[4]; uint4 u; } O;
    #pragma unroll
    for (int u = 0; u < 4; ++u)
        O.hh[u] = __floats2half2_rn(e[2 * u] * rinv, e[2 * u + 1] * rinv);
    *op = O.u;
}

// ---------------------------------------------------------------------------
extern "C" void kernel_launch(void* const* d_in, const int* in_sizes, int n_in,
                              void* d_out, int out_size)
{
    const float* sq   = (const float*)d_in[0];
    const float* skv  = (const float*)d_in[1];
    const int*   qpad = (const int*)d_in[2];
    const int*   kpad = (const int*)d_in[3];
    const float* Wq   = (const float*)d_in[4];
    const float* Wk   = (const float*)d_in[5];
    const float* Wv   = (const float*)d_in[6];
    float* out = (float*)d_out;

    float *Sb;
    __half *sqh, *sql, *kvh, *kvl, *wq16, *wk16, *wvh, *wvl;
    __half *q16, *k16, *vt16, *p16;
    cudaGetSymbolAddress((void**)&Sb,   g_S);
    cudaGetSymbolAddress((void**)&sqh,  g_sqh);  cudaGetSymbolAddress((void**)&sql, g_sql);
    cudaGetSymbolAddress((void**)&kvh,  g_kvh);  cudaGetSymbolAddress((void**)&kvl, g_kvl);
    cudaGetSymbolAddress((void**)&wq16, g_wq16); cudaGetSymbolAddress((void**)&wk16, g_wk16);
    cudaGetSymbolAddress((void**)&wvh,  g_wvh);  cudaGetSymbolAddress((void**)&wvl, g_wvl);
    cudaGetSymbolAddress((void**)&q16,  g_q16);  cudaGetSymbolAddress((void**)&k16, g_k16);
    cudaGetSymbolAddress((void**)&vt16, g_vt16);
    cudaGetSymbolAddress((void**)&p16,  g_p16);

    const int SMEMSZ = 98304;   // 3 x (16 KB A + 16 KB B)
    cudaFuncSetAttribute(proj3_kernel,
                         cudaFuncAttributeMaxDynamicSharedMemorySize, SMEMSZ);
    cudaFuncSetAttribute(scores_kernel,
                         cudaFuncAttributeMaxDynamicSharedMemorySize, SMEMSZ);
    cudaFuncSetAttribute(attnv_kernel,
                         cudaFuncAttributeMaxDynamicSharedMemorySize, SMEMSZ);

    // 1) split both sources to fp16 hi/lo (one launch)
    const int nsrc = MTOK * DM;                    // 16.7M
    split2_kernel<<<dim3(nsrc / 2048, 2), 256>>>(sq, sqh, sql, skv, kvh, kvl);
    // 2) transpose weights: Wq,Wk single fp16; Wv fp16 hi/lo (one launch)
    splitw3_kernel<<<dim3((DK * DM) / 256, 3), 256>>>(
        Wq, wq16, Wk, wk16, Wv, wvh, wvl);

    // 3) all three projections in ONE launch (1536 CTAs), 2-segment fp16
    proj3_kernel<<<1536, 128, SMEMSZ>>>(
        sqh, sql, kvh, kvl, wq16, wk16, wvh, wvl, q16, k16, vt16);

    // 4) scores S_b = Q_b * K_b^T (1-term fp16, causal tile-skip), fp32 epilogue
    scores_kernel<<<dim3(SS / 128, SS / 128, BB), 128, SMEMSZ>>>(q16, k16, Sb);

    // 5) mask + softmax -> P fp16
    const float scale = 0.04419417382415922f;   // 1/sqrt(512)
    softmax_f16<<<MTOK, 256>>>(Sb, p16, qpad, kpad, scale);

    // 6) O_b = P_b * V_b (1-term fp16, K truncated at causal diagonal,
    //    longest-first order)
    attnv_kernel<<<dim3(DV / 128, SS / 128, BB), 128, SMEMSZ>>>(
        p16, vt16, out);
}

// round 15
// speedup vs baseline: 2.0949x; 1.0085x over previous
#include <cuda_runtime.h>
#include <cuda_bf16.h>
#include <cuda_fp16.h>
#include <stdint.h>
#include <math.h>

#define BB 8
#define SS 2048
#define DM 1024
#define DK 512
#define DV 512
#define MTOK (BB*SS)   // 16384

// ---------------- scratch (static device allocations) ----------------
__device__ __align__(256) float  g_S   [(size_t)BB*SS*SS];    // 134 MB scores
__device__ __align__(256) __half g_sqh [(size_t)MTOK*DM];     // sq fp16 hi
__device__ __align__(256) __half g_sql [(size_t)MTOK*DM];     // sq fp16 lo
__device__ __align__(256) __half g_kvh [(size_t)MTOK*DM];     // kv fp16 hi (also single-fp16 kv)
__device__ __align__(256) __half g_kvl [(size_t)MTOK*DM];     // kv fp16 lo
__device__ __align__(256) __half g_wq16[(size_t)DK*DM];       // Wq^T single fp16
__device__ __align__(256) __half g_wk16[(size_t)DK*DM];       // Wk^T single fp16
__device__ __align__(256) __half g_wvh [(size_t)DV*DM];       // Wv^T fp16 hi
__device__ __align__(256) __half g_wvl [(size_t)DV*DM];       // Wv^T fp16 lo
__device__ __align__(256) __half g_q16 [(size_t)MTOK*DK];     // Q fp16
__device__ __align__(256) __half g_k16 [(size_t)MTOK*DK];     // K fp16
__device__ __align__(256) __half g_vt16[(size_t)DV*MTOK];     // V^T fp16 [512 x 16384]
__device__ __align__(256) __half g_p16 [(size_t)MTOK*SS];     // P fp16 (67 MB)

// ---------------- portable PTX helpers (sm_80+ only) ----------
__device__ __forceinline__ uint32_t s2u(const void* p) {
    return (uint32_t)__cvta_generic_to_shared(p);
}

#define CPA16(dst, src) \
    asm volatile("cp.async.cg.shared.global [%0], [%1], 16;" :: "r"(dst), "l"(src))

#define CPA_COMMIT() asm volatile("cp.async.commit_group;" ::: "memory")
#define CPA_WAIT0()  asm volatile("cp.async.wait_group 0;" ::: "memory")
#define CPA_WAIT1()  asm volatile("cp.async.wait_group 1;" ::: "memory")

#define LDSM_X4(r, addr) \
    asm volatile("ldmatrix.sync.aligned.m8n8.x4.shared.b16 {%0,%1,%2,%3}, [%4];" \
        : "=r"((r)[0]), "=r"((r)[1]), "=r"((r)[2]), "=r"((r)[3]) : "r"(addr))

#define MMA16816H(d, a, b) \
    asm volatile("mma.sync.aligned.m16n8k16.row.col.f32.f16.f16.f32 " \
        "{%0,%1,%2,%3}, {%4,%5,%6,%7}, {%8,%9}, {%0,%1,%2,%3};" \
        : "+f"((d)[0]), "+f"((d)[1]), "+f"((d)[2]), "+f"((d)[3]) \
        : "r"((a)[0]), "r"((a)[1]), "r"((a)[2]), "r"((a)[3]), \
          "r"((b)[0]), "r"((b)[1]))

// ---------------------------------------------------------------------------
// Shared fp16 GEMM core.
//   NSEG==2: acc += A0*B0^T + A1*B0^T   (A exact via hi/lo split, B quantized)
//   NSEG==1: acc += A0*B0^T
//   4 warps (2x2), warp tile 64x64, BK=64, 3-stage cp.async pipeline,
//   single-sync mainloop. Caller provides 96 KB dynamic smem.
//   Smem row = 64 elems = 128 B = 8 x 16B chunks; chunk c stored at c^(row&7).
//   KTRUNC: per-segment K truncated at bm0+128 (attn*V causal)
// ---------------------------------------------------------------------------
template <int NSEG, bool KTRUNC>
__device__ __forceinline__ void gemm_core(
    const __half* __restrict__ A0, const __half* __restrict__ A1,
    const __half* __restrict__ B0,
    int bm0, int bn0, int segK, int ldA, int ldB,
    float acc[4][8][4])
{
    extern __shared__ char sm[];
    const uint32_t smb = s2u(sm);
    const uint32_t aBuf[3] = { smb,         smb + 32768, smb + 65536 };
    const uint32_t bBuf[3] = { smb + 16384, smb + 49152, smb + 81920 };

    const int tid = threadIdx.x, wid = tid >> 5, lane = tid & 31;
    const int warp_m = (wid >> 1) * 64;   // 0 or 64
    const int warp_n = (wid & 1) * 64;    // 0 or 64

    int kEnd = segK;
    if (KTRUNC) { int l = bm0 + 128; kEnd = (l < segK) ? l : segK; }
    const int cps   = kEnd >> 6;          // 64-elem chunks per segment
    const int total = NSEG * cps;

    auto load_chunk = [&](int c, int buf) {
        int seg = (NSEG == 1) ? 0 : (c / cps);
        int ck  = (NSEG == 1) ? c : (c - seg * cps);
        const __half* Aseg = (seg == 1) ? A1 : A0;
        const __half* gA = Aseg + (size_t)bm0 * ldA + (ck << 6);
        const __half* gB = B0   + (size_t)bn0 * ldB + (ck << 6);
        const uint32_t bA = aBuf[buf], bB = bBuf[buf];
        #pragma unroll
        for (int t = 0; t < 8; ++t) {
            int f = tid + t * 128;            // 0..1023
            int row = f >> 3, cch = f & 7;
            int sw = cch ^ (row & 7);
            CPA16(bA + row * 128 + sw * 16, (const char*)(gA + (size_t)row * ldA) + cch * 16);
            CPA16(bB + row * 128 + sw * 16, (const char*)(gB + (size_t)row * ldB) + cch * 16);
        }
        CPA_COMMIT();
    };

    load_chunk(0, 0);
    load_chunk(1, 1);
    CPA_WAIT1();
    __syncthreads();

    const int wi = lane & 7, g = lane >> 3;   // ldmatrix lane-group decomposition

    int buf = 0;
    for (int c = 0; c < total; ++c) {
        const uint32_t bA = aBuf[buf], bB = bBuf[buf];
        int nb = buf + 2; if (nb >= 3) nb -= 3;

        #pragma unroll
        for (int ks = 0; ks < 4; ++ks) {
            if (ks == 1 && c + 2 < total) load_chunk(c + 2, nb);

            uint32_t a[4][4];
            #pragma unroll
            for (int mf = 0; mf < 4; ++mf) {
                int row = warp_m + mf * 16 + (g & 1) * 8 + wi;
                int cch = 2 * ks + (g >> 1);
                LDSM_X4(a[mf], bA + row * 128 + (cch ^ (row & 7)) * 16);
            }
            uint32_t b[8][2];
            #pragma unroll
            for (int p = 0; p < 4; ++p) {
                uint32_t r[4];
                int row = warp_n + p * 16 + (g >> 1) * 8 + wi;
                int cch = 2 * ks + (g & 1);
                LDSM_X4(r, bB + row * 128 + (cch ^ (row & 7)) * 16);
                b[2 * p + 0][0] = r[0]; b[2 * p + 0][1] = r[1];
                b[2 * p + 1][0] = r[2]; b[2 * p + 1][1] = r[3];
            }
            #pragma unroll
            for (int mf = 0; mf < 4; ++mf)
                #pragma unroll
                for (int nf = 0; nf < 8; ++nf)
                    MMA16816H(acc[mf][nf], a[mf], b[nf]);
        }

        if (c + 1 < total) {
            if (c + 2 < total) { CPA_WAIT1(); } else { CPA_WAIT0(); }
            __syncthreads();
        }
        if (++buf == 3) buf = 0;
    }
}

// epilogue: fp32 store. c-frag map: c0,c1 -> (lane/4, (lane%4)*2), c2,c3 -> row+8
__device__ __forceinline__ void epi_f32(
    float acc[4][8][4], float* __restrict__ Cf, int bm0, int bn0, int ldC)
{
    const int tid = threadIdx.x, wid = tid >> 5, lane = tid & 31;
    const int warp_m = (wid >> 1) * 64, warp_n = (wid & 1) * 64;
    const int rq = lane >> 2, cq = (lane & 3) * 2;
    #pragma unroll
    for (int mf = 0; mf < 4; ++mf)
        #pragma unroll
        for (int nf = 0; nf < 8; ++nf) {
            int m0 = bm0 + warp_m + mf * 16 + rq;
            int n0 = bn0 + warp_n + nf * 8 + cq;
            *(float2*)(Cf + (size_t)m0 * ldC + n0) =
                make_float2(acc[mf][nf][0], acc[mf][nf][1]);
            *(float2*)(Cf + (size_t)(m0 + 8) * ldC + n0) =
                make_float2(acc[mf][nf][2], acc[mf][nf][3]);
        }
}

// epilogue: single fp16 store
__device__ __forceinline__ void epi_f16(
    float acc[4][8][4], __half* __restrict__ C, int bm0, int bn0, int ldC)
{
    const int tid = threadIdx.x, wid = tid >> 5, lane = tid & 31;
    const int warp_m = (wid >> 1) * 64, warp_n = (wid & 1) * 64;
    const int rq = lane >> 2, cq = (lane & 3) * 2;
    #pragma unroll
    for (int mf = 0; mf < 4; ++mf)
        #pragma unroll
        for (int nf = 0; nf < 8; ++nf) {
            int m0 = bm0 + warp_m + mf * 16 + rq;
            int n0 = bn0 + warp_n + nf * 8 + cq;
            #pragma unroll
            for (int h = 0; h < 2; ++h) {
                __half2 v = __floats2half2_rn(acc[mf][nf][2 * h + 0],
                                              acc[mf][nf][2 * h + 1]);
                *(__half2*)(C + (size_t)(m0 + 8 * h) * ldC + n0) = v;
            }
        }
}

// ---------------------------------------------------------------------------
// All three projections in ONE launch (1536 CTAs), all 2-segment fp16:
//   Q : A = sq hi/lo,  B = Wq^T single     -> fp16 out
//   K : A = kv hi/lo,  B = Wk^T single     -> fp16 out
//   Vt: A = Wv^T hi/lo, B = kv hi (single) -> fp16 out (produced transposed)
// blockIdx.x: [0,512) -> Q, [512,1024) -> K, [1024,1536) -> Vt
// ---------------------------------------------------------------------------
__global__ void __launch_bounds__(128, 2) proj3_kernel(
    const __half* __restrict__ sqh, const __half* __restrict__ sql,
    const __half* __restrict__ kvh, const __half* __restrict__ kvl,
    const __half* __restrict__ wq16, const __half* __restrict__ wk16,
    const __half* __restrict__ wvh, const __half* __restrict__ wvl,
    __half* __restrict__ q16, __half* __restrict__ k16,
    __half* __restrict__ vt16)
{
    const int bx = blockIdx.x;
    const int p = bx >> 9;        // 0,1,2
    const int t = bx & 511;
    float acc[4][8][4] = {};
    if (p == 0) {
        int bm0 = (t >> 2) * 128, bn0 = (t & 3) * 128;
        gemm_core<2, false>(sqh, sql, wq16, bm0, bn0, DM, DM, DM, acc);
        epi_f16(acc, q16, bm0, bn0, DK);
    } else if (p == 1) {
        int bm0 = (t >> 2) * 128, bn0 = (t & 3) * 128;
        gemm_core<2, false>(kvh, kvl, wk16, bm0, bn0, DM, DM, DM, acc);
        epi_f16(acc, k16, bm0, bn0, DK);
    } else {
        int bm0 = (t & 3) * 128, bn0 = (t >> 2) * 128;
        gemm_core<2, false>(wvh, wvl, kvh, bm0, bn0, DM, DM, DM, acc);
        epi_f16(acc, vt16, bm0, bn0, MTOK);
    }
}

// ---------------------------------------------------------------------------
// Scores: S_b = Q_b * K_b^T, 1-term fp16, causal tile-skip, fp32 epilogue
// ---------------------------------------------------------------------------
__global__ void __launch_bounds__(128, 2) scores_kernel(
    const __half* __restrict__ q16, const __half* __restrict__ k16,
    float* __restrict__ Sb)
{
    const int bn0 = blockIdx.x * 128;
    const int bm0 = blockIdx.y * 128;
    if (bn0 >= bm0 + 128) return;    // above causal diagonal
    const long long z = blockIdx.z;
    const long long soff = z * (long long)SS * DK;
    float acc[4][8][4] = {};
    gemm_core<1, false>(q16 + soff, nullptr, k16 + soff,
                        bm0, bn0, DK, DK, DK, acc);
    epi_f32(acc, Sb + z * (long long)SS * SS, bm0, bn0, SS);
}

// ---------------------------------------------------------------------------
// attn*V: O_b = P_b * V_b, 1-term fp16, K truncated at causal diagonal.
// bm order REVERSED (longest-work CTAs first).
// ---------------------------------------------------------------------------
__global__ void __launch_bounds__(128, 2) attnv_kernel(
    const __half* __restrict__ p16, const __half* __restrict__ vt16,
    float* __restrict__ out)
{
    const int bn0 = blockIdx.x * 128;
    const int bm0 = (gridDim.y - 1 - blockIdx.y) * 128;   // longest first
    const long long z = blockIdx.z;
    float acc[4][8][4] = {};
    gemm_core<1, true>(p16 + z * (long long)SS * SS, nullptr,
                       vt16 + z * (long long)SS,
                       bm0, bn0, SS, SS, MTOK, acc);
    epi_f32(acc, out + z * (long long)SS * DV, bm0, bn0, DV);
}

// ---------------------------------------------------------------------------
// fp32 -> fp16 (hi, lo) split for both sources in one launch (grid.y selects)
// ---------------------------------------------------------------------------
__global__ void __launch_bounds__(256) split2_kernel(
    const float* __restrict__ x0, __half* __restrict__ h0, __half* __restrict__ l0,
    const float* __restrict__ x1, __half* __restrict__ h1, __half* __restrict__ l1)
{
    const float* x = blockIdx.y ? x1 : x0;
    __half* h = blockIdx.y ? h1 : h0;
    __half* l = blockIdx.y ? l1 : l0;
    int i = (blockIdx.x * 256 + threadIdx.x) * 8;
    float4 a = *(const float4*)(x + i);
    float4 b = *(const float4*)(x + i + 4);
    float v[8] = {a.x, a.y, a.z, a.w, b.x, b.y, b.z, b.w};
    union { __half hh[8]; uint4 u; } H, L;
    #pragma unroll
    for (int j = 0; j < 8; ++j) {
        __half hv = __float2half_rn(v[j]);
        H.hh[j] = hv;
        L.hh[j] = __float2half_rn(v[j] - __half2float(hv));
    }
    *(uint4*)(h + i) = H.u;
    *(uint4*)(l + i) = L.u;
}

// Weights fp32 [DM x 512] -> transposed fp16 [512 x DM].
// grid.y: 0 -> Wq single, 1 -> Wk single, 2 -> Wv hi/lo
__global__ void __launch_bounds__(256) splitw3_kernel(
    const float* __restrict__ W0, __half* __restrict__ o0,
    const float* __restrict__ W1, __half* __restrict__ o1,
    const float* __restrict__ W2, __half* __restrict__ h2, __half* __restrict__ l2)
{
    int o = blockIdx.x * 256 + threadIdx.x;   // o = n*DM + k, n<512
    int n = o >> 10, k = o & 1023;
    if (blockIdx.y == 0) {
        o0[o] = __float2half_rn(W0[(size_t)k * 512 + n]);
    } else if (blockIdx.y == 1) {
        o1[o] = __float2half_rn(W1[(size_t)k * 512 + n]);
    } else {
        float v = W2[(size_t)k * 512 + n];
        __half hv = __float2half_rn(v);
        h2[o] = hv;
        l2[o] = __float2half_rn(v - __half2float(hv));
    }
}

// ---------------------------------------------------------------------------
// fused mask + softmax reading fp32 scores, writing fp16 probabilities
// ---------------------------------------------------------------------------
__global__ void __launch_bounds__(256) softmax_f16(
    const float* __restrict__ S, __half* __restrict__ P,
    const int* __restrict__ qpad, const int* __restrict__ kpad, float scale)
{
    const int r = blockIdx.x;
    const int b = r >> 11, i = r & (SS - 1);
    const float* row = S + (size_t)r * SS;
    const int* kp = kpad + b * SS;
    const bool qp = (qpad[r] != 0);
    const int tid = threadIdx.x, j0 = tid * 8;
    const int lane = tid & 31, warp = tid >> 5;

    float4 a = ((const float4*)(row + j0))[0];
    float4 c = ((const float4*)(row + j0))[1];
    int4 ka = ((const int4*)(kp + j0))[0];
    int4 kb = ((const int4*)(kp + j0))[1];
    float x[8] = {a.x, a.y, a.z, a.w, c.x, c.y, c.z, c.w};
    int km[8] = {ka.x, ka.y, ka.z, ka.w, kb.x, kb.y, kb.z, kb.w};

    float m = -INFINITY;
    #pragma unroll
    for (int u = 0; u < 8; ++u) {
        bool valid = (!qp) && (j0 + u <= i) && (km[u] == 0);
        x[u] = valid ? x[u] * scale : -INFINITY;
        m = fmaxf(m, x[u]);
    }

    __shared__ float redm[8], reds[8];
    #pragma unroll
    for (int o = 16; o; o >>= 1) m = fmaxf(m, __shfl_xor_sync(0xffffffffu, m, o));
    if (lane == 0) redm[warp] = m;
    __syncthreads();
    float bm = -INFINITY;
    #pragma unroll
    for (int w = 0; w < 8; ++w) bm = fmaxf(bm, redm[w]);

    uint4* op = (uint4*)(P + (size_t)r * SS + j0);

    if (bm == -INFINITY) {     // fully masked row -> zeros
        *op = make_uint4(0, 0, 0, 0);
        return;
    }

    float e[8];
    float s = 0.0f;
    #pragma unroll
    for (int u = 0; u < 8; ++u) {
        e[u] = (x[u] == -INFINITY) ? 0.0f : __expf(x[u] - bm);
        s += e[u];
    }
    #pragma unroll
    for (int o = 16; o; o >>= 1) s += __shfl_xor_sync(0xffffffffu, s, o);
    if (lane == 0) reds[warp] = s;
    __syncthreads();
    float bs = 0.0f;
    #pragma unroll
    for (int w = 0; w < 8; ++w) bs += reds[w];

    const float rinv = 1.0f / bs;
    union { __half2 hh[4]; uint4 u; } O;
    #pragma unroll
    for (int u = 0; u < 4; ++u)
        O.hh[u] = __floats2half2_rn(e[2 * u] * rinv, e[2 * u + 1] * rinv);
    *op = O.u;
}

// ---------------------------------------------------------------------------
extern "C" void kernel_launch(void* const* d_in, const int* in_sizes, int n_in,
                              void* d_out, int out_size)
{
    const float* sq   = (const float*)d_in[0];
    const float* skv  = (const float*)d_in[1];
    const int*   qpad = (const int*)d_in[2];
    const int*   kpad = (const int*)d_in[3];
    const float* Wq   = (const float*)d_in[4];
    const float* Wk   = (const float*)d_in[5];
    const float* Wv   = (const float*)d_in[6];
    float* out = (float*)d_out;

    float *Sb;
    __half *sqh, *sql, *kvh, *kvl, *wq16, *wk16, *wvh, *wvl;
    __half *q16, *k16, *vt16, *p16;
    cudaGetSymbolAddress((void**)&Sb,   g_S);
    cudaGetSymbolAddress((void**)&sqh,  g_sqh);  cudaGetSymbolAddress((void**)&sql, g_sql);
    cudaGetSymbolAddress((void**)&kvh,  g_kvh);  cudaGetSymbolAddress((void**)&kvl, g_kvl);
    cudaGetSymbolAddress((void**)&wq16, g_wq16); cudaGetSymbolAddress((void**)&wk16, g_wk16);
    cudaGetSymbolAddress((void**)&wvh,  g_wvh);  cudaGetSymbolAddress((void**)&wvl, g_wvl);
    cudaGetSymbolAddress((void**)&q16,  g_q16);  cudaGetSymbolAddress((void**)&k16, g_k16);
    cudaGetSymbolAddress((void**)&vt16, g_vt16);
    cudaGetSymbolAddress((void**)&p16,  g_p16);

    const int SMEMSZ = 98304;   // 3 x (16 KB A + 16 KB B)
    cudaFuncSetAttribute(proj3_kernel,
                         cudaFuncAttributeMaxDynamicSharedMemorySize, SMEMSZ);
    cudaFuncSetAttribute(scores_kernel,
                         cudaFuncAttributeMaxDynamicSharedMemorySize, SMEMSZ);
    cudaFuncSetAttribute(attnv_kernel,
                         cudaFuncAttributeMaxDynamicSharedMemorySize, SMEMSZ);

    // 1) split both sources to fp16 hi/lo (one launch)
    const int nsrc = MTOK * DM;                    // 16.7M
    split2_kernel<<<dim3(nsrc / 2048, 2), 256>>>(sq, sqh, sql, skv, kvh, kvl);
    // 2) transpose weights: Wq,Wk single fp16; Wv fp16 hi/lo (one launch)
    splitw3_kernel<<<dim3((DK * DM) / 256, 3), 256>>>(
        Wq, wq16, Wk, wk16, Wv, wvh, wvl);

    // 3) all three projections in ONE launch (1536 CTAs), 2-segment fp16
    proj3_kernel<<<1536, 128, SMEMSZ>>>(
        sqh, sql, kvh, kvl, wq16, wk16, wvh, wvl, q16, k16, vt16);

    // 4) scores S_b = Q_b * K_b^T (1-term fp16, causal tile-skip), fp32 epilogue
    scores_kernel<<<dim3(SS / 128, SS / 128, BB), 128, SMEMSZ>>>(q16, k16, Sb);

    // 5) mask + softmax -> P fp16
    const float scale = 0.04419417382415922f;   // 1/sqrt(512)
    softmax_f16<<<MTOK, 256>>>(Sb, p16, qpad, kpad, scale);

    // 6) O_b = P_b * V_b (1-term fp16, K truncated at causal diagonal,
    //    longest-first order)
    attnv_kernel<<<dim3(DV / 128, SS / 128, BB), 128, SMEMSZ>>>(
        p16, vt16, out);
}

// round 16
// speedup vs baseline: 2.0982x; 1.0016x over previous
#include <cuda_runtime.h>
#include <cuda_bf16.h>
#include <cuda_fp16.h>
#include <stdint.h>
#include <math.h>

#define BB 8
#define SS 2048
#define DM 1024
#define DK 512
#define DV 512
#define MTOK (BB*SS)   // 16384

// ---------------- scratch (static device allocations) ----------------
__device__ __align__(256) float  g_S   [(size_t)BB*SS*SS];    // 134 MB scores
__device__ __align__(256) __half g_sqh [(size_t)MTOK*DM];     // sq fp16 hi
__device__ __align__(256) __half g_sql [(size_t)MTOK*DM];     // sq fp16 lo
__device__ __align__(256) __half g_kvh [(size_t)MTOK*DM];     // kv fp16 hi (also single-fp16 kv)
__device__ __align__(256) __half g_kvl [(size_t)MTOK*DM];     // kv fp16 lo
__device__ __align__(256) __half g_wq16[(size_t)DK*DM];       // Wq^T single fp16
__device__ __align__(256) __half g_wk16[(size_t)DK*DM];       // Wk^T single fp16
__device__ __align__(256) __half g_wvh [(size_t)DV*DM];       // Wv^T fp16 hi
__device__ __align__(256) __half g_wvl [(size_t)DV*DM];       // Wv^T fp16 lo
__device__ __align__(256) __half g_q16 [(size_t)MTOK*DK];     // Q fp16
__device__ __align__(256) __half g_k16 [(size_t)MTOK*DK];     // K fp16
__device__ __align__(256) __half g_vt16[(size_t)DV*MTOK];     // V^T fp16 [512 x 16384]
__device__ __align__(256) __half g_p16 [(size_t)MTOK*SS];     // P fp16 (67 MB)

// ---------------- portable PTX helpers (sm_80+ only) ----------
__device__ __forceinline__ uint32_t s2u(const void* p) {
    return (uint32_t)__cvta_generic_to_shared(p);
}

#define CPA16(dst, src) \
    asm volatile("cp.async.cg.shared.global [%0], [%1], 16;" :: "r"(dst), "l"(src))

#define CPA_COMMIT() asm volatile("cp.async.commit_group;" ::: "memory")
#define CPA_WAIT0()  asm volatile("cp.async.wait_group 0;" ::: "memory")
#define CPA_WAIT1()  asm volatile("cp.async.wait_group 1;" ::: "memory")

#define LDSM_X4(r, addr) \
    asm volatile("ldmatrix.sync.aligned.m8n8.x4.shared.b16 {%0,%1,%2,%3}, [%4];" \
        : "=r"((r)[0]), "=r"((r)[1]), "=r"((r)[2]), "=r"((r)[3]) : "r"(addr))

#define MMA16816H(d, a, b) \
    asm volatile("mma.sync.aligned.m16n8k16.row.col.f32.f16.f16.f32 " \
        "{%0,%1,%2,%3}, {%4,%5,%6,%7}, {%8,%9}, {%0,%1,%2,%3};" \
        : "+f"((d)[0]), "+f"((d)[1]), "+f"((d)[2]), "+f"((d)[3]) \
        : "r"((a)[0]), "r"((a)[1]), "r"((a)[2]), "r"((a)[3]), \
          "r"((b)[0]), "r"((b)[1]))

// ---------------------------------------------------------------------------
// Shared fp16 GEMM core.
//   NSEG==2: acc += A0*B0^T + A1*B0^T   (A exact via hi/lo split, B quantized)
//   NSEG==1: acc += A0*B0^T
//   4 warps (2x2), warp tile 64x64, BK=64, 3-stage cp.async pipeline,
//   single-sync mainloop. Caller provides 96 KB dynamic smem.
//   Smem row = 64 elems = 128 B = 8 x 16B chunks; chunk c stored at c^(row&7).
//   KTRUNC: per-segment K truncated at bm0+128 (attn*V causal)
// ---------------------------------------------------------------------------
template <int NSEG, bool KTRUNC>
__device__ __forceinline__ void gemm_core(
    const __half* __restrict__ A0, const __half* __restrict__ A1,
    const __half* __restrict__ B0,
    int bm0, int bn0, int segK, int ldA, int ldB,
    float acc[4][8][4])
{
    extern __shared__ char sm[];
    const uint32_t smb = s2u(sm);
    const uint32_t aBuf[3] = { smb,         smb + 32768, smb + 65536 };
    const uint32_t bBuf[3] = { smb + 16384, smb + 49152, smb + 81920 };

    const int tid = threadIdx.x, wid = tid >> 5, lane = tid & 31;
    const int warp_m = (wid >> 1) * 64;   // 0 or 64
    const int warp_n = (wid & 1) * 64;    // 0 or 64

    int kEnd = segK;
    if (KTRUNC) { int l = bm0 + 128; kEnd = (l < segK) ? l : segK; }
    const int cps   = kEnd >> 6;          // 64-elem chunks per segment
    const int total = NSEG * cps;

    auto load_chunk = [&](int c, int buf) {
        int seg = (NSEG == 1) ? 0 : (c / cps);
        int ck  = (NSEG == 1) ? c : (c - seg * cps);
        const __half* Aseg = (seg == 1) ? A1 : A0;
        const __half* gA = Aseg + (size_t)bm0 * ldA + (ck << 6);
        const __half* gB = B0   + (size_t)bn0 * ldB + (ck << 6);
        const uint32_t bA = aBuf[buf], bB = bBuf[buf];
        #pragma unroll
        for (int t = 0; t < 8; ++t) {
            int f = tid + t * 128;            // 0..1023
            int row = f >> 3, cch = f & 7;
            int sw = cch ^ (row & 7);
            CPA16(bA + row * 128 + sw * 16, (const char*)(gA + (size_t)row * ldA) + cch * 16);
            CPA16(bB + row * 128 + sw * 16, (const char*)(gB + (size_t)row * ldB) + cch * 16);
        }
        CPA_COMMIT();
    };

    load_chunk(0, 0);
    load_chunk(1, 1);
    CPA_WAIT1();
    __syncthreads();

    const int wi = lane & 7, g = lane >> 3;   // ldmatrix lane-group decomposition

    int buf = 0;
    for (int c = 0; c < total; ++c) {
        const uint32_t bA = aBuf[buf], bB = bBuf[buf];
        int nb = buf + 2; if (nb >= 3) nb -= 3;

        #pragma unroll
        for (int ks = 0; ks < 4; ++ks) {
            if (ks == 1 && c + 2 < total) load_chunk(c + 2, nb);

            uint32_t a[4][4];
            #pragma unroll
            for (int mf = 0; mf < 4; ++mf) {
                int row = warp_m + mf * 16 + (g & 1) * 8 + wi;
                int cch = 2 * ks + (g >> 1);
                LDSM_X4(a[mf], bA + row * 128 + (cch ^ (row & 7)) * 16);
            }
            uint32_t b[8][2];
            #pragma unroll
            for (int p = 0; p < 4; ++p) {
                uint32_t r[4];
                int row = warp_n + p * 16 + (g >> 1) * 8 + wi;
                int cch = 2 * ks + (g & 1);
                LDSM_X4(r, bB + row * 128 + (cch ^ (row & 7)) * 16);
                b[2 * p + 0][0] = r[0]; b[2 * p + 0][1] = r[1];
                b[2 * p + 1][0] = r[2]; b[2 * p + 1][1] = r[3];
            }
            #pragma unroll
            for (int mf = 0; mf < 4; ++mf)
                #pragma unroll
                for (int nf = 0; nf < 8; ++nf)
                    MMA16816H(acc[mf][nf], a[mf], b[nf]);
        }

        if (c + 1 < total) {
            if (c + 2 < total) { CPA_WAIT1(); } else { CPA_WAIT0(); }
            __syncthreads();
        }
        if (++buf == 3) buf = 0;
    }
}

// epilogue: fp32 store. c-frag map: c0,c1 -> (lane/4, (lane%4)*2), c2,c3 -> row+8
__device__ __forceinline__ void epi_f32(
    float acc[4][8][4], float* __restrict__ Cf, int bm0, int bn0, int ldC)
{
    const int tid = threadIdx.x, wid = tid >> 5, lane = tid & 31;
    const int warp_m = (wid >> 1) * 64, warp_n = (wid & 1) * 64;
    const int rq = lane >> 2, cq = (lane & 3) * 2;
    #pragma unroll
    for (int mf = 0; mf < 4; ++mf)
        #pragma unroll
        for (int nf = 0; nf < 8; ++nf) {
            int m0 = bm0 + warp_m + mf * 16 + rq;
            int n0 = bn0 + warp_n + nf * 8 + cq;
            *(float2*)(Cf + (size_t)m0 * ldC + n0) =
                make_float2(acc[mf][nf][0], acc[mf][nf][1]);
            *(float2*)(Cf + (size_t)(m0 + 8) * ldC + n0) =
                make_float2(acc[mf][nf][2], acc[mf][nf][3]);
        }
}

// epilogue: single fp16 store
__device__ __forceinline__ void epi_f16(
    float acc[4][8][4], __half* __restrict__ C, int bm0, int bn0, int ldC)
{
    const int tid = threadIdx.x, wid = tid >> 5, lane = tid & 31;
    const int warp_m = (wid >> 1) * 64, warp_n = (wid & 1) * 64;
    const int rq = lane >> 2, cq = (lane & 3) * 2;
    #pragma unroll
    for (int mf = 0; mf < 4; ++mf)
        #pragma unroll
        for (int nf = 0; nf < 8; ++nf) {
            int m0 = bm0 + warp_m + mf * 16 + rq;
            int n0 = bn0 + warp_n + nf * 8 + cq;
            #pragma unroll
            for (int h = 0; h < 2; ++h) {
                __half2 v = __floats2half2_rn(acc[mf][nf][2 * h + 0],
                                              acc[mf][nf][2 * h + 1]);
                *(__half2*)(C + (size_t)(m0 + 8 * h) * ldC + n0) = v;
            }
        }
}

// ---------------------------------------------------------------------------
// All three projections in ONE launch (1536 CTAs), all 2-segment fp16:
//   Q : A = sq hi/lo,  B = Wq^T single     -> fp16 out
//   K : A = kv hi/lo,  B = Wk^T single     -> fp16 out
//   Vt: A = Wv^T hi/lo, B = kv hi (single) -> fp16 out (produced transposed)
// blockIdx.x: [0,512) -> Q, [512,1024) -> K, [1024,1536) -> Vt
// ---------------------------------------------------------------------------
__global__ void __launch_bounds__(128, 2) proj3_kernel(
    const __half* __restrict__ sqh, const __half* __restrict__ sql,
    const __half* __restrict__ kvh, const __half* __restrict__ kvl,
    const __half* __restrict__ wq16, const __half* __restrict__ wk16,
    const __half* __restrict__ wvh, const __half* __restrict__ wvl,
    __half* __restrict__ q16, __half* __restrict__ k16,
    __half* __restrict__ vt16)
{
    const int bx = blockIdx.x;
    const int p = bx >> 9;        // 0,1,2
    const int t = bx & 511;
    float acc[4][8][4] = {};
    if (p == 0) {
        int bm0 = (t >> 2) * 128, bn0 = (t & 3) * 128;
        gemm_core<2, false>(sqh, sql, wq16, bm0, bn0, DM, DM, DM, acc);
        epi_f16(acc, q16, bm0, bn0, DK);
    } else if (p == 1) {
        int bm0 = (t >> 2) * 128, bn0 = (t & 3) * 128;
        gemm_core<2, false>(kvh, kvl, wk16, bm0, bn0, DM, DM, DM, acc);
        epi_f16(acc, k16, bm0, bn0, DK);
    } else {
        int bm0 = (t & 3) * 128, bn0 = (t >> 2) * 128;
        gemm_core<2, false>(wvh, wvl, kvh, bm0, bn0, DM, DM, DM, acc);
        epi_f16(acc, vt16, bm0, bn0, MTOK);
    }
}

// ---------------------------------------------------------------------------
// Scores: S_b = Q_b * K_b^T, 1-term fp16, causal tile-skip, fp32 epilogue
// ---------------------------------------------------------------------------
__global__ void __launch_bounds__(128, 2) scores_kernel(
    const __half* __restrict__ q16, const __half* __restrict__ k16,
    float* __restrict__ Sb)
{
    const int bn0 = blockIdx.x * 128;
    const int bm0 = blockIdx.y * 128;
    if (bn0 >= bm0 + 128) return;    // above causal diagonal
    const long long z = blockIdx.z;
    const long long soff = z * (long long)SS * DK;
    float acc[4][8][4] = {};
    gemm_core<1, false>(q16 + soff, nullptr, k16 + soff,
                        bm0, bn0, DK, DK, DK, acc);
    epi_f32(acc, Sb + z * (long long)SS * SS, bm0, bn0, SS);
}

// ---------------------------------------------------------------------------
// attn*V: O_b = P_b * V_b, 1-term fp16, K truncated at causal diagonal.
// bm order REVERSED (longest-work CTAs first).
// ---------------------------------------------------------------------------
__global__ void __launch_bounds__(128, 2) attnv_kernel(
    const __half* __restrict__ p16, const __half* __restrict__ vt16,
    float* __restrict__ out)
{
    const int bn0 = blockIdx.x * 128;
    const int bm0 = (gridDim.y - 1 - blockIdx.y) * 128;   // longest first
    const long long z = blockIdx.z;
    float acc[4][8][4] = {};
    gemm_core<1, true>(p16 + z * (long long)SS * SS, nullptr,
                       vt16 + z * (long long)SS,
                       bm0, bn0, SS, SS, MTOK, acc);
    epi_f32(acc, out + z * (long long)SS * DV, bm0, bn0, DV);
}

// ---------------------------------------------------------------------------
// fp32 -> fp16 (hi, lo) split for both sources in one launch (grid.y selects)
// ---------------------------------------------------------------------------
__global__ void __launch_bounds__(256) split2_kernel(
    const float* __restrict__ x0, __half* __restrict__ h0, __half* __restrict__ l0,
    const float* __restrict__ x1, __half* __restrict__ h1, __half* __restrict__ l1)
{
    const float* x = blockIdx.y ? x1 : x0;
    __half* h = blockIdx.y ? h1 : h0;
    __half* l = blockIdx.y ? l1 : l0;
    int i = (blockIdx.x * 256 + threadIdx.x) * 8;
    float4 a = *(const float4*)(x + i);
    float4 b = *(const float4*)(x + i + 4);
    float v[8] = {a.x, a.y, a.z, a.w, b.x, b.y, b.z, b.w};
    union { __half hh[8]; uint4 u; } H, L;
    #pragma unroll
    for (int j = 0; j < 8; ++j) {
        __half hv = __float2half_rn(v[j]);
        H.hh[j] = hv;
        L.hh[j] = __float2half_rn(v[j] - __half2float(hv));
    }
    *(uint4*)(h + i) = H.u;
    *(uint4*)(l + i) = L.u;
}

// Weights fp32 [DM x 512] -> transposed fp16 [512 x DM].
// grid.y: 0 -> Wq single, 1 -> Wk single, 2 -> Wv hi/lo
__global__ void __launch_bounds__(256) splitw3_kernel(
    const float* __restrict__ W0, __half* __restrict__ o0,
    const float* __restrict__ W1, __half* __restrict__ o1,
    const float* __restrict__ W2, __half* __restrict__ h2, __half* __restrict__ l2)
{
    int o = blockIdx.x * 256 + threadIdx.x;   // o = n*DM + k, n<512
    int n = o >> 10, k = o & 1023;
    if (blockIdx.y == 0) {
        o0[o] = __float2half_rn(W0[(size_t)k * 512 + n]);
    } else if (blockIdx.y == 1) {
        o1[o] = __float2half_rn(W1[(size_t)k * 512 + n]);
    } else {
        float v = W2[(size_t)k * 512 + n];
        __half hv = __float2half_rn(v);
        h2[o] = hv;
        l2[o] = __float2half_rn(v - __half2float(hv));
    }
}

// ---------------------------------------------------------------------------
// fused mask + softmax reading fp32 scores, writing fp16 probabilities
// ---------------------------------------------------------------------------
__global__ void __launch_bounds__(256) softmax_f16(
    const float* __restrict__ S, __half* __restrict__ P,
    const int* __restrict__ qpad, const int* __restrict__ kpad, float scale)
{
    const int r = blockIdx.x;
    const int b = r >> 11, i = r & (SS - 1);
    const float* row = S + (size_t)r * SS;
    const int* kp = kpad + b * SS;
    const bool qp = (qpad[r] != 0);
    const int tid = threadIdx.x, j0 = tid * 8;
    const int lane = tid & 31, warp = tid >> 5;

    float4 a = ((const float4*)(row + j0))[0];
    float4 c = ((const float4*)(row + j0))[1];
    int4 ka = ((const int4*)(kp + j0))[0];
    int4 kb = ((const int4*)(kp + j0))[1];
    float x[8] = {a.x, a.y, a.z, a.w, c.x, c.y, c.z, c.w};
    int km[8] = {ka.x, ka.y, ka.z, ka.w, kb.x, kb.y, kb.z, kb.w};

    float m = -INFINITY;
    #pragma unroll
    for (int u = 0; u < 8; ++u) {
        bool valid = (!qp) && (j0 + u <= i) && (km[u] == 0);
        x[u] = valid ? x[u] * scale : -INFINITY;
        m = fmaxf(m, x[u]);
    }

    __shared__ float redm[8], reds[8];
    #pragma unroll
    for (int o = 16; o; o >>= 1) m = fmaxf(m, __shfl_xor_sync(0xffffffffu, m, o));
    if (lane == 0) redm[warp] = m;
    __syncthreads();
    float bm = -INFINITY;
    #pragma unroll
    for (int w = 0; w < 8; ++w) bm = fmaxf(bm, redm[w]);

    uint4* op = (uint4*)(P + (size_t)r * SS + j0);

    if (bm == -INFINITY) {     // fully masked row -> zeros
        *op = make_uint4(0, 0, 0, 0);
        return;
    }

    float e[8];
    float s = 0.0f;
    #pragma unroll
    for (int u = 0; u < 8; ++u) {
        e[u] = (x[u] == -INFINITY) ? 0.0f : __expf(x[u] - bm);
        s += e[u];
    }
    #pragma unroll
    for (int o = 16; o; o >>= 1) s += __shfl_xor_sync(0xffffffffu, s, o);
    if (lane == 0) reds[warp] = s;
    __syncthreads();
    float bs = 0.0f;
    #pragma unroll
    for (int w = 0; w < 8; ++w) bs += reds[w];

    const float rinv = 1.0f / bs;
    union { __half2 hh[4]; uint4 u; } O;
    #pragma unroll
    for (int u = 0; u < 4; ++u)
        O.hh[u] = __floats2half2_rn(e[2 * u] * rinv, e[2 * u + 1] * rinv);
    *op = O.u;
}

// ---------------------------------------------------------------------------
extern "C" void kernel_launch(void* const* d_in, const int* in_sizes, int n_in,
                              void* d_out, int out_size)
{
    const float* sq   = (const float*)d_in[0];
    const float* skv  = (const float*)d_in[1];
    const int*   qpad = (const int*)d_in[2];
    const int*   kpad = (const int*)d_in[3];
    const float* Wq   = (const float*)d_in[4];
    const float* Wk   = (const float*)d_in[5];
    const float* Wv   = (const float*)d_in[6];
    float* out = (float*)d_out;

    float *Sb;
    __half *sqh, *sql, *kvh, *kvl, *wq16, *wk16, *wvh, *wvl;
    __half *q16, *k16, *vt16, *p16;
    cudaGetSymbolAddress((void**)&Sb,   g_S);
    cudaGetSymbolAddress((void**)&sqh,  g_sqh);  cudaGetSymbolAddress((void**)&sql, g_sql);
    cudaGetSymbolAddress((void**)&kvh,  g_kvh);  cudaGetSymbolAddress((void**)&kvl, g_kvl);
    cudaGetSymbolAddress((void**)&wq16, g_wq16); cudaGetSymbolAddress((void**)&wk16, g_wk16);
    cudaGetSymbolAddress((void**)&wvh,  g_wvh);  cudaGetSymbolAddress((void**)&wvl, g_wvl);
    cudaGetSymbolAddress((void**)&q16,  g_q16);  cudaGetSymbolAddress((void**)&k16, g_k16);
    cudaGetSymbolAddress((void**)&vt16, g_vt16);
    cudaGetSymbolAddress((void**)&p16,  g_p16);

    const int SMEMSZ = 98304;   // 3 x (16 KB A + 16 KB B)
    cudaFuncSetAttribute(proj3_kernel,
                         cudaFuncAttributeMaxDynamicSharedMemorySize, SMEMSZ);
    cudaFuncSetAttribute(scores_kernel,
                         cudaFuncAttributeMaxDynamicSharedMemorySize, SMEMSZ);
    cudaFuncSetAttribute(attnv_kernel,
                         cudaFuncAttributeMaxDynamicSharedMemorySize, SMEMSZ);

    // 1) split both sources to fp16 hi/lo (one launch)
    const int nsrc = MTOK * DM;                    // 16.7M
    split2_kernel<<<dim3(nsrc / 2048, 2), 256>>>(sq, sqh, sql, skv, kvh, kvl);
    // 2) transpose weights: Wq,Wk single fp16; Wv fp16 hi/lo (one launch)
    splitw3_kernel<<<dim3((DK * DM) / 256, 3), 256>>>(
        Wq, wq16, Wk, wk16, Wv, wvh, wvl);

    // 3) all three projections in ONE launch (1536 CTAs), 2-segment fp16
    proj3_kernel<<<1536, 128, SMEMSZ>>>(
        sqh, sql, kvh, kvl, wq16, wk16, wvh, wvl, q16, k16, vt16);

    // 4) scores S_b = Q_b * K_b^T (1-term fp16, causal tile-skip), fp32 epilogue
    scores_kernel<<<dim3(SS / 128, SS / 128, BB), 128, SMEMSZ>>>(q16, k16, Sb);

    // 5) mask + softmax -> P fp16
    const float scale = 0.04419417382415922f;   // 1/sqrt(512)
    softmax_f16<<<MTOK, 256>>>(Sb, p16, qpad, kpad, scale);

    // 6) O_b = P_b * V_b (1-term fp16, K truncated at causal diagonal,
    //    longest-first order)
    attnv_kernel<<<dim3(DV / 128, SS / 128, BB), 128, SMEMSZ>>>(
        p16, vt16, out);
}